// round 2
// baseline (speedup 1.0000x reference)
#include <cuda_runtime.h>
#include <math.h>

// Problem constants (b=1, c=512, t=16, h=w=32)
#define C_DIM 512
#define T_FR 16
#define HW 1024          // h*w tokens per frame
#define S_TOT 16384      // t*h*w
#define NG 32            // groups
#define CPG 16           // channels per group

// ---------------- scratch (device globals; no allocation allowed) ----------
__device__ float g_hn[C_DIM * S_TOT];        // 32 MB  group-normed, channel-major [c][s]
__device__ float g_q [S_TOT * C_DIM];        // 32 MB  token-major [s][c]
__device__ float g_k [S_TOT * C_DIM];        // 32 MB
__device__ float g_v [S_TOT * C_DIM];        // 32 MB
__device__ float g_p [T_FR * HW * HW];       // 64 MB  attention scores/probs
__device__ float g_ao[S_TOT * C_DIM];        // 32 MB  attention output, token-major
__device__ float g_mean[NG];
__device__ float g_rstd[NG];

// ---------------- GroupNorm statistics ------------------------------------
__global__ void gn_stats(const float* __restrict__ x) {
    int g = blockIdx.x;
    const float* xp = x + (size_t)g * CPG * S_TOT;
    const int n = CPG * S_TOT;
    float s = 0.f, ss = 0.f;
    for (int i = threadIdx.x; i < n; i += blockDim.x) {
        float v = xp[i];
        s += v; ss += v * v;
    }
    __shared__ float rs[256], rss[256];
    rs[threadIdx.x] = s; rss[threadIdx.x] = ss;
    __syncthreads();
    for (int off = 128; off > 0; off >>= 1) {
        if (threadIdx.x < off) {
            rs[threadIdx.x]  += rs[threadIdx.x + off];
            rss[threadIdx.x] += rss[threadIdx.x + off];
        }
        __syncthreads();
    }
    if (threadIdx.x == 0) {
        float inv_n = 1.0f / (float)n;
        float m = rs[0] * inv_n;
        float var = rss[0] * inv_n - m * m;
        g_mean[g] = m;
        g_rstd[g] = rsqrtf(var + 1e-6f);
    }
}

// ---------------- GroupNorm apply ------------------------------------------
__global__ void gn_apply(const float* __restrict__ x,
                         const float* __restrict__ gamma,
                         const float* __restrict__ beta) {
    int idx = blockIdx.x * blockDim.x + threadIdx.x;
    if (idx >= C_DIM * S_TOT) return;
    int c = idx / S_TOT;
    int g = c / CPG;
    g_hn[idx] = (x[idx] - g_mean[g]) * g_rstd[g] * gamma[c] + beta[c];
}

// ---------------- GEMM 1: QKV projections ----------------------------------
// out[s][o] = sum_c hn[c][s] * W[o][c] + bias[o]
// M = S_TOT tokens, N = C_DIM outputs, K = C_DIM. Tile 64x64, BK=16.
__global__ void gemm_qkv(const float* __restrict__ wq, const float* __restrict__ bq,
                         const float* __restrict__ wk, const float* __restrict__ bk,
                         const float* __restrict__ wv, const float* __restrict__ bv) {
    const float* W; const float* B; float* out;
    if (blockIdx.z == 0)      { W = wq; B = bq; out = g_q; }
    else if (blockIdx.z == 1) { W = wk; B = bk; out = g_k; }
    else                      { W = wv; B = bv; out = g_v; }

    __shared__ float As[16][68];   // [k][m]  from g_hn
    __shared__ float Bs[16][68];   // [k][n]  from W
    const int m0 = blockIdx.x * 64;
    const int n0 = blockIdx.y * 64;
    const int tx = threadIdx.x, ty = threadIdx.y;
    const int tid = ty * 16 + tx;
    float acc[4][4] = {};

    for (int k0 = 0; k0 < C_DIM; k0 += 16) {
        // hn is contiguous along m -> map e so mm varies fastest
        #pragma unroll
        for (int e = tid; e < 16 * 64; e += 256) {
            int kk = e >> 6, mm = e & 63;
            As[kk][mm] = g_hn[(k0 + kk) * S_TOT + m0 + mm];
        }
        // W is contiguous along k -> map e so kk varies fastest
        #pragma unroll
        for (int e = tid; e < 16 * 64; e += 256) {
            int kk = e & 15, nn = e >> 4;
            Bs[kk][nn] = W[(n0 + nn) * C_DIM + k0 + kk];
        }
        __syncthreads();
        #pragma unroll
        for (int kk = 0; kk < 16; kk++) {
            float a[4], b[4];
            #pragma unroll
            for (int i = 0; i < 4; i++) a[i] = As[kk][ty * 4 + i];
            #pragma unroll
            for (int j = 0; j < 4; j++) b[j] = Bs[kk][tx * 4 + j];
            #pragma unroll
            for (int i = 0; i < 4; i++)
                #pragma unroll
                for (int j = 0; j < 4; j++)
                    acc[i][j] += a[i] * b[j];
        }
        __syncthreads();
    }
    #pragma unroll
    for (int i = 0; i < 4; i++) {
        int m = m0 + ty * 4 + i;
        #pragma unroll
        for (int j = 0; j < 4; j++) {
            int n = n0 + tx * 4 + j;
            out[m * C_DIM + n] = acc[i][j] + B[n];
        }
    }
}

// ---------------- GEMM 2: S = scale * Q K^T (batched over frames) ----------
// M = N = 1024 tokens, K = 512.
__global__ void gemm_qk(float scale) {
    const int f = blockIdx.z;
    const float* Q  = g_q + (size_t)f * HW * C_DIM;
    const float* Km = g_k + (size_t)f * HW * C_DIM;
    float* P = g_p + (size_t)f * HW * HW;

    __shared__ float As[16][68];   // [k][m] from Q
    __shared__ float Bs[16][68];   // [k][n] from K
    const int m0 = blockIdx.x * 64;
    const int n0 = blockIdx.y * 64;
    const int tx = threadIdx.x, ty = threadIdx.y;
    const int tid = ty * 16 + tx;
    float acc[4][4] = {};

    for (int k0 = 0; k0 < C_DIM; k0 += 16) {
        // Q,K row-major (contiguous along k) -> kk varies fastest
        #pragma unroll
        for (int e = tid; e < 16 * 64; e += 256) {
            int kk = e & 15, mm = e >> 4;
            As[kk][mm] = Q[(m0 + mm) * C_DIM + k0 + kk];
        }
        #pragma unroll
        for (int e = tid; e < 16 * 64; e += 256) {
            int kk = e & 15, nn = e >> 4;
            Bs[kk][nn] = Km[(n0 + nn) * C_DIM + k0 + kk];
        }
        __syncthreads();
        #pragma unroll
        for (int kk = 0; kk < 16; kk++) {
            float a[4], b[4];
            #pragma unroll
            for (int i = 0; i < 4; i++) a[i] = As[kk][ty * 4 + i];
            #pragma unroll
            for (int j = 0; j < 4; j++) b[j] = Bs[kk][tx * 4 + j];
            #pragma unroll
            for (int i = 0; i < 4; i++)
                #pragma unroll
                for (int j = 0; j < 4; j++)
                    acc[i][j] += a[i] * b[j];
        }
        __syncthreads();
    }
    #pragma unroll
    for (int i = 0; i < 4; i++) {
        int m = m0 + ty * 4 + i;
        #pragma unroll
        for (int j = 0; j < 4; j++) {
            int n = n0 + tx * 4 + j;
            P[m * HW + n] = acc[i][j] * scale;
        }
    }
}

// ---------------- row softmax (16384 rows of 1024) --------------------------
__global__ void softmax_rows() {
    const int row = blockIdx.x;
    float* p = g_p + (size_t)row * HW;
    const int tid = threadIdx.x;

    float v[4];
    float mx = -1e30f;
    #pragma unroll
    for (int i = 0; i < 4; i++) { v[i] = p[tid + i * 256]; mx = fmaxf(mx, v[i]); }

    __shared__ float red[256];
    red[tid] = mx; __syncthreads();
    for (int off = 128; off > 0; off >>= 1) {
        if (tid < off) red[tid] = fmaxf(red[tid], red[tid + off]);
        __syncthreads();
    }
    mx = red[0]; __syncthreads();

    float s = 0.f;
    #pragma unroll
    for (int i = 0; i < 4; i++) { v[i] = expf(v[i] - mx); s += v[i]; }
    red[tid] = s; __syncthreads();
    for (int off = 128; off > 0; off >>= 1) {
        if (tid < off) red[tid] += red[tid + off];
        __syncthreads();
    }
    float inv = 1.0f / red[0];
    #pragma unroll
    for (int i = 0; i < 4; i++) p[tid + i * 256] = v[i] * inv;
}

// ---------------- GEMM 3: O = P V (batched over frames) --------------------
// M = 1024 tokens, N = 512 channels, K = 1024 keys.
__global__ void gemm_av() {
    const int f = blockIdx.z;
    const float* P = g_p + (size_t)f * HW * HW;
    const float* V = g_v + (size_t)f * HW * C_DIM;
    float* O = g_ao + (size_t)f * HW * C_DIM;

    __shared__ float As[16][68];   // [k][m] from P
    __shared__ float Bs[16][68];   // [k][n] from V
    const int m0 = blockIdx.x * 64;
    const int n0 = blockIdx.y * 64;
    const int tx = threadIdx.x, ty = threadIdx.y;
    const int tid = ty * 16 + tx;
    float acc[4][4] = {};

    for (int k0 = 0; k0 < HW; k0 += 16) {
        // P row-major (contiguous along k)
        #pragma unroll
        for (int e = tid; e < 16 * 64; e += 256) {
            int kk = e & 15, mm = e >> 4;
            As[kk][mm] = P[(m0 + mm) * HW + k0 + kk];
        }
        // V contiguous along n
        #pragma unroll
        for (int e = tid; e < 16 * 64; e += 256) {
            int kk = e >> 6, nn = e & 63;
            Bs[kk][nn] = V[(k0 + kk) * C_DIM + n0 + nn];
        }
        __syncthreads();
        #pragma unroll
        for (int kk = 0; kk < 16; kk++) {
            float a[4], b[4];
            #pragma unroll
            for (int i = 0; i < 4; i++) a[i] = As[kk][ty * 4 + i];
            #pragma unroll
            for (int j = 0; j < 4; j++) b[j] = Bs[kk][tx * 4 + j];
            #pragma unroll
            for (int i = 0; i < 4; i++)
                #pragma unroll
                for (int j = 0; j < 4; j++)
                    acc[i][j] += a[i] * b[j];
        }
        __syncthreads();
    }
    #pragma unroll
    for (int i = 0; i < 4; i++) {
        int m = m0 + ty * 4 + i;
        #pragma unroll
        for (int j = 0; j < 4; j++) {
            int n = n0 + tx * 4 + j;
            O[m * C_DIM + n] = acc[i][j];
        }
    }
}

// ---------------- GEMM 4: out proj + bias + residual -----------------------
// y[o][s] = sum_c wo[o][c] * ao[s][c] + bo[o] + x[o][s]
// M = 512 output channels, N = 16384 positions, K = 512.
__global__ void gemm_out(const float* __restrict__ wo, const float* __restrict__ bo,
                         const float* __restrict__ x, float* __restrict__ y) {
    __shared__ float As[16][68];   // [k][m] from wo
    __shared__ float Bs[16][68];   // [k][n] from ao
    const int m0 = blockIdx.x * 64;   // output channel
    const int n0 = blockIdx.y * 64;   // spatial position
    const int tx = threadIdx.x, ty = threadIdx.y;
    const int tid = ty * 16 + tx;
    float acc[4][4] = {};

    for (int k0 = 0; k0 < C_DIM; k0 += 16) {
        // wo row-major (contiguous along k)
        #pragma unroll
        for (int e = tid; e < 16 * 64; e += 256) {
            int kk = e & 15, mm = e >> 4;
            As[kk][mm] = wo[(m0 + mm) * C_DIM + k0 + kk];
        }
        // ao row-major over [s][c]: contiguous along k(=c)
        #pragma unroll
        for (int e = tid; e < 16 * 64; e += 256) {
            int kk = e & 15, nn = e >> 4;
            Bs[kk][nn] = g_ao[(n0 + nn) * C_DIM + k0 + kk];
        }
        __syncthreads();
        #pragma unroll
        for (int kk = 0; kk < 16; kk++) {
            float a[4], b[4];
            #pragma unroll
            for (int i = 0; i < 4; i++) a[i] = As[kk][ty * 4 + i];
            #pragma unroll
            for (int j = 0; j < 4; j++) b[j] = Bs[kk][tx * 4 + j];
            #pragma unroll
            for (int i = 0; i < 4; i++)
                #pragma unroll
                for (int j = 0; j < 4; j++)
                    acc[i][j] += a[i] * b[j];
        }
        __syncthreads();
    }
    #pragma unroll
    for (int i = 0; i < 4; i++) {
        int m = m0 + ty * 4 + i;
        float bias = bo[m];
        #pragma unroll
        for (int j = 0; j < 4; j++) {
            int n = n0 + tx * 4 + j;
            y[m * S_TOT + n] = acc[i][j] + bias + x[m * S_TOT + n];
        }
    }
}

// ---------------- launch ----------------------------------------------------
extern "C" void kernel_launch(void* const* d_in, const int* in_sizes, int n_in,
                              void* d_out, int out_size) {
    const float* x     = (const float*)d_in[0];
    const float* gamma = (const float*)d_in[1];
    const float* beta  = (const float*)d_in[2];
    const float* wq    = (const float*)d_in[3];
    const float* bq    = (const float*)d_in[4];
    const float* wk    = (const float*)d_in[5];
    const float* bk    = (const float*)d_in[6];
    const float* wv    = (const float*)d_in[7];
    const float* bv    = (const float*)d_in[8];
    const float* wo    = (const float*)d_in[9];
    const float* bo    = (const float*)d_in[10];
    float* y = (float*)d_out;

    dim3 t2d(16, 16);

    gn_stats<<<NG, 256>>>(x);
    gn_apply<<<(C_DIM * S_TOT + 255) / 256, 256>>>(x, gamma, beta);

    // QKV: grid (tokens/64, outch/64, 3)
    gemm_qkv<<<dim3(S_TOT / 64, C_DIM / 64, 3), t2d>>>(wq, bq, wk, bk, wv, bv);

    // scores: grid (1024/64, 1024/64, 16 frames)
    const float scale = 0.044194173824159216f;  // 512^-0.5
    gemm_qk<<<dim3(HW / 64, HW / 64, T_FR), t2d>>>(scale);

    softmax_rows<<<S_TOT, 256>>>();

    gemm_av<<<dim3(HW / 64, C_DIM / 64, T_FR), t2d>>>();

    gemm_out<<<dim3(C_DIM / 64, S_TOT / 64), t2d>>>(wo, bo, x, y);
}

// round 4
// speedup vs baseline: 3.0095x; 3.0095x over previous
#include <cuda_runtime.h>
#include <math.h>

// Problem constants (b=1, c=512, t=16, h=w=32)
#define C_DIM 512
#define T_FR 16
#define HW 1024          // h*w tokens per frame
#define S_TOT 16384      // t*h*w
#define NG 32            // groups
#define CPG 16           // channels per group

// ---------------- scratch (device globals; no allocation allowed) ----------
__device__ __align__(16) float g_hn[S_TOT * C_DIM];        // token-major [s][c]
__device__ __align__(16) float g_q [S_TOT * C_DIM];        // [s][c]
__device__ __align__(16) float g_k [S_TOT * C_DIM];        // [s][c]
__device__ __align__(16) float g_v [S_TOT * C_DIM];        // [s][c]
__device__ __align__(16) float g_vt[T_FR * C_DIM * HW];    // [f][c][j]
__device__ __align__(16) float g_p [T_FR * HW * HW];       // [f][i][j]
__device__ __align__(16) float g_ao[S_TOT * C_DIM];        // [s][c]
__device__ float g_mean[NG];
__device__ float g_rstd[NG];

// ---------------- GroupNorm statistics ------------------------------------
__global__ void gn_stats(const float* __restrict__ x) {
    int g = blockIdx.x;
    const float* xp = x + (size_t)g * CPG * S_TOT;
    const int n = CPG * S_TOT;
    float s = 0.f, ss = 0.f;
    for (int i = threadIdx.x; i < n; i += blockDim.x) {
        float v = xp[i];
        s += v; ss += v * v;
    }
    __shared__ float rs[256], rss[256];
    rs[threadIdx.x] = s; rss[threadIdx.x] = ss;
    __syncthreads();
    for (int off = 128; off > 0; off >>= 1) {
        if (threadIdx.x < off) {
            rs[threadIdx.x]  += rs[threadIdx.x + off];
            rss[threadIdx.x] += rss[threadIdx.x + off];
        }
        __syncthreads();
    }
    if (threadIdx.x == 0) {
        float inv_n = 1.0f / (float)n;
        float m = rs[0] * inv_n;
        float var = rss[0] * inv_n - m * m;
        g_mean[g] = m;
        g_rstd[g] = rsqrtf(var + 1e-6f);
    }
}

// ---------------- GroupNorm apply + transpose to token-major ---------------
// x is [c][s]; write g_hn as [s][c].
__global__ void gn_apply_t(const float* __restrict__ x,
                           const float* __restrict__ gamma,
                           const float* __restrict__ beta) {
    __shared__ float tile[32][33];
    const int s0 = blockIdx.x * 32;
    const int c0 = blockIdx.y * 32;
    const int tx = threadIdx.x, ty = threadIdx.y;
    #pragma unroll
    for (int j = 0; j < 4; j++) {
        int cl = ty + j * 8;
        tile[cl][tx] = x[(size_t)(c0 + cl) * S_TOT + s0 + tx];
    }
    __syncthreads();
    int c = c0 + tx;
    int g = c >> 4;   // CPG = 16
    float m = g_mean[g], r = g_rstd[g];
    float ga = gamma[c], be = beta[c];
    #pragma unroll
    for (int j = 0; j < 4; j++) {
        int sl = ty + j * 8;
        g_hn[(size_t)(s0 + sl) * C_DIM + c] = (tile[tx][sl] - m) * r * ga + be;
    }
}

// ---------------- per-frame V transpose: [s][c] -> [f][c][j] ----------------
__global__ void v_transpose() {
    __shared__ float tile[32][33];
    const int f  = blockIdx.z;
    const int j0 = blockIdx.x * 32;
    const int c0 = blockIdx.y * 32;
    const int tx = threadIdx.x, ty = threadIdx.y;
    #pragma unroll
    for (int i = 0; i < 4; i++) {
        int jl = ty + i * 8;
        tile[jl][tx] = g_v[(size_t)(f * HW + j0 + jl) * C_DIM + c0 + tx];
    }
    __syncthreads();
    #pragma unroll
    for (int i = 0; i < 4; i++) {
        int cl = ty + i * 8;
        g_vt[(size_t)(f * C_DIM + c0 + cl) * HW + j0 + tx] = tile[tx][cl];
    }
}

// ---------------- tf32 tensor-core GEMM core --------------------------------
// out[m][n] = sum_k A[m][k] * B[n][k]   (both K-contiguous, "NT")
// Block tile 128x128, BK=16, 256 threads = 8 warps (2x4), warp tile 64x32,
// per-warp 4x4 mma grid of m16n8k8.

#define BKP 20   // 16 + 4 padding (uints)

__device__ __forceinline__ unsigned f2tf32(float f) {
    unsigned u;
    asm("cvt.rna.tf32.f32 %0, %1;" : "=r"(u) : "f"(f));
    return u;
}

__device__ __forceinline__ void mma_tf32(float c[4],
                                         unsigned a0, unsigned a1, unsigned a2, unsigned a3,
                                         unsigned b0, unsigned b1) {
    asm volatile(
        "mma.sync.aligned.m16n8k8.row.col.f32.tf32.tf32.f32 "
        "{%0,%1,%2,%3},{%4,%5,%6,%7},{%8,%9},{%0,%1,%2,%3};\n"
        : "+f"(c[0]), "+f"(c[1]), "+f"(c[2]), "+f"(c[3])
        : "r"(a0), "r"(a1), "r"(a2), "r"(a3), "r"(b0), "r"(b1));
}

__device__ __forceinline__ void gemm_core(const float* __restrict__ A,
                                          const float* __restrict__ B,
                                          int lda, int ldb, int K,
                                          float acc[4][4][4]) {
    __shared__ unsigned As[128 * BKP];
    __shared__ unsigned Bs[128 * BKP];
    const int tid  = threadIdx.x;
    const int lane = tid & 31;
    const int warp = tid >> 5;
    const int g    = lane >> 2;
    const int tig  = lane & 3;
    const int wm   = (warp >> 2) * 64;
    const int wn   = (warp & 3) * 32;

    for (int k0 = 0; k0 < K; k0 += 16) {
        #pragma unroll
        for (int u = 0; u < 2; u++) {
            int fidx = tid + u * 256;
            int row  = fidx >> 2;
            int kq   = (fidx & 3) * 4;
            float4 av = *reinterpret_cast<const float4*>(A + (size_t)row * lda + k0 + kq);
            unsigned* da = &As[row * BKP + kq];
            da[0] = f2tf32(av.x); da[1] = f2tf32(av.y);
            da[2] = f2tf32(av.z); da[3] = f2tf32(av.w);
            float4 bv = *reinterpret_cast<const float4*>(B + (size_t)row * ldb + k0 + kq);
            unsigned* db = &Bs[row * BKP + kq];
            db[0] = f2tf32(bv.x); db[1] = f2tf32(bv.y);
            db[2] = f2tf32(bv.z); db[3] = f2tf32(bv.w);
        }
        __syncthreads();
        #pragma unroll
        for (int k8 = 0; k8 < 2; k8++) {
            unsigned af[4][4], bf[4][2];
            #pragma unroll
            for (int mi = 0; mi < 4; mi++) {
                const unsigned* p = &As[(wm + mi * 16 + g) * BKP + k8 * 8 + tig];
                af[mi][0] = p[0];
                af[mi][1] = p[8 * BKP];
                af[mi][2] = p[4];
                af[mi][3] = p[8 * BKP + 4];
            }
            #pragma unroll
            for (int ni = 0; ni < 4; ni++) {
                const unsigned* p = &Bs[(wn + ni * 8 + g) * BKP + k8 * 8 + tig];
                bf[ni][0] = p[0];
                bf[ni][1] = p[4];
            }
            #pragma unroll
            for (int mi = 0; mi < 4; mi++)
                #pragma unroll
                for (int ni = 0; ni < 4; ni++)
                    mma_tf32(acc[mi][ni],
                             af[mi][0], af[mi][1], af[mi][2], af[mi][3],
                             bf[ni][0], bf[ni][1]);
        }
        __syncthreads();
    }
}

// Epilogue index helpers (D fragment of m16n8k8):
//   r0 = m0 + wm + mi*16 + g ; r1 = r0 + 8 ; c = n0 + wn + ni*8 + 2*tig (c, c+1)

// ---------------- GEMM 1: QKV projections -----------------------------------
__global__ void __launch_bounds__(256) k_qkv(
        const float* __restrict__ wq, const float* __restrict__ bq,
        const float* __restrict__ wk, const float* __restrict__ bk,
        const float* __restrict__ wv, const float* __restrict__ bv) {
    const float* W; const float* Bi; float* out;
    if (blockIdx.z == 0)      { W = wq; Bi = bq; out = g_q; }
    else if (blockIdx.z == 1) { W = wk; Bi = bk; out = g_k; }
    else                      { W = wv; Bi = bv; out = g_v; }
    const int m0 = blockIdx.x * 128;   // token
    const int n0 = blockIdx.y * 128;   // out channel
    float acc[4][4][4] = {};
    gemm_core(g_hn + (size_t)m0 * C_DIM, W + (size_t)n0 * C_DIM, C_DIM, C_DIM, C_DIM, acc);

    const int tid = threadIdx.x, lane = tid & 31, warp = tid >> 5;
    const int g = lane >> 2, tig = lane & 3;
    const int wm = (warp >> 2) * 64, wn = (warp & 3) * 32;
    #pragma unroll
    for (int mi = 0; mi < 4; mi++) {
        int r0 = m0 + wm + mi * 16 + g;
        #pragma unroll
        for (int ni = 0; ni < 4; ni++) {
            int c = n0 + wn + ni * 8 + 2 * tig;
            float b0v = Bi[c], b1v = Bi[c + 1];
            out[(size_t)r0 * C_DIM + c]           = acc[mi][ni][0] + b0v;
            out[(size_t)r0 * C_DIM + c + 1]       = acc[mi][ni][1] + b1v;
            out[(size_t)(r0 + 8) * C_DIM + c]     = acc[mi][ni][2] + b0v;
            out[(size_t)(r0 + 8) * C_DIM + c + 1] = acc[mi][ni][3] + b1v;
        }
    }
}

// ---------------- GEMM 2: S = scale * Q K^T (batched frames) ----------------
__global__ void __launch_bounds__(256) k_qk(float scale) {
    const int f  = blockIdx.z;
    const int m0 = blockIdx.x * 128;
    const int n0 = blockIdx.y * 128;
    const float* Q  = g_q + (size_t)f * HW * C_DIM + (size_t)m0 * C_DIM;
    const float* Km = g_k + (size_t)f * HW * C_DIM + (size_t)n0 * C_DIM;
    float* P = g_p + (size_t)f * HW * HW;
    float acc[4][4][4] = {};
    gemm_core(Q, Km, C_DIM, C_DIM, C_DIM, acc);

    const int tid = threadIdx.x, lane = tid & 31, warp = tid >> 5;
    const int g = lane >> 2, tig = lane & 3;
    const int wm = (warp >> 2) * 64, wn = (warp & 3) * 32;
    #pragma unroll
    for (int mi = 0; mi < 4; mi++) {
        int r0 = m0 + wm + mi * 16 + g;
        #pragma unroll
        for (int ni = 0; ni < 4; ni++) {
            int c = n0 + wn + ni * 8 + 2 * tig;
            P[(size_t)r0 * HW + c]           = acc[mi][ni][0] * scale;
            P[(size_t)r0 * HW + c + 1]       = acc[mi][ni][1] * scale;
            P[(size_t)(r0 + 8) * HW + c]     = acc[mi][ni][2] * scale;
            P[(size_t)(r0 + 8) * HW + c + 1] = acc[mi][ni][3] * scale;
        }
    }
}

// ---------------- row softmax (16384 rows of 1024) ---------------------------
__global__ void softmax_rows() {
    const int row = blockIdx.x;
    float* p = g_p + (size_t)row * HW;
    const int tid = threadIdx.x;

    float v[4];
    float mx = -1e30f;
    #pragma unroll
    for (int i = 0; i < 4; i++) { v[i] = p[tid + i * 256]; mx = fmaxf(mx, v[i]); }

    __shared__ float red[256];
    red[tid] = mx; __syncthreads();
    for (int off = 128; off > 0; off >>= 1) {
        if (tid < off) red[tid] = fmaxf(red[tid], red[tid + off]);
        __syncthreads();
    }
    mx = red[0]; __syncthreads();

    float s = 0.f;
    #pragma unroll
    for (int i = 0; i < 4; i++) { v[i] = expf(v[i] - mx); s += v[i]; }
    red[tid] = s; __syncthreads();
    for (int off = 128; off > 0; off >>= 1) {
        if (tid < off) red[tid] += red[tid + off];
        __syncthreads();
    }
    float inv = 1.0f / red[0];
    #pragma unroll
    for (int i = 0; i < 4; i++) p[tid + i * 256] = v[i] * inv;
}

// ---------------- GEMM 3: O = P V (batched frames) ---------------------------
__global__ void __launch_bounds__(256) k_pv() {
    const int f  = blockIdx.z;
    const int m0 = blockIdx.x * 128;   // query token
    const int n0 = blockIdx.y * 128;   // channel
    const float* P  = g_p  + (size_t)f * HW * HW + (size_t)m0 * HW;
    const float* Vt = g_vt + (size_t)f * C_DIM * HW + (size_t)n0 * HW;
    float acc[4][4][4] = {};
    gemm_core(P, Vt, HW, HW, HW, acc);

    const int tid = threadIdx.x, lane = tid & 31, warp = tid >> 5;
    const int g = lane >> 2, tig = lane & 3;
    const int wm = (warp >> 2) * 64, wn = (warp & 3) * 32;
    float* O = g_ao + (size_t)f * HW * C_DIM;
    #pragma unroll
    for (int mi = 0; mi < 4; mi++) {
        int r0 = m0 + wm + mi * 16 + g;
        #pragma unroll
        for (int ni = 0; ni < 4; ni++) {
            int c = n0 + wn + ni * 8 + 2 * tig;
            O[(size_t)r0 * C_DIM + c]           = acc[mi][ni][0];
            O[(size_t)r0 * C_DIM + c + 1]       = acc[mi][ni][1];
            O[(size_t)(r0 + 8) * C_DIM + c]     = acc[mi][ni][2];
            O[(size_t)(r0 + 8) * C_DIM + c + 1] = acc[mi][ni][3];
        }
    }
}

// ---------------- GEMM 4: out proj + bias + residual ------------------------
// y[o][s] = sum_c wo[o][c] * ao[s][c] + bo[o] + x[o][s]
__global__ void __launch_bounds__(256) k_out(
        const float* __restrict__ wo, const float* __restrict__ bo,
        const float* __restrict__ x, float* __restrict__ y) {
    const int m0 = blockIdx.x * 128;   // out channel
    const int n0 = blockIdx.y * 128;   // spatial position
    float acc[4][4][4] = {};
    gemm_core(wo + (size_t)m0 * C_DIM, g_ao + (size_t)n0 * C_DIM, C_DIM, C_DIM, C_DIM, acc);

    const int tid = threadIdx.x, lane = tid & 31, warp = tid >> 5;
    const int g = lane >> 2, tig = lane & 3;
    const int wm = (warp >> 2) * 64, wn = (warp & 3) * 32;
    #pragma unroll
    for (int mi = 0; mi < 4; mi++) {
        int r0 = m0 + wm + mi * 16 + g;
        float bo0 = bo[r0], bo1 = bo[r0 + 8];
        #pragma unroll
        for (int ni = 0; ni < 4; ni++) {
            int c = n0 + wn + ni * 8 + 2 * tig;
            size_t i00 = (size_t)r0 * S_TOT + c;
            size_t i10 = (size_t)(r0 + 8) * S_TOT + c;
            y[i00]     = acc[mi][ni][0] + bo0 + x[i00];
            y[i00 + 1] = acc[mi][ni][1] + bo0 + x[i00 + 1];
            y[i10]     = acc[mi][ni][2] + bo1 + x[i10];
            y[i10 + 1] = acc[mi][ni][3] + bo1 + x[i10 + 1];
        }
    }
}

// ---------------- launch ------------------------------------------------------
extern "C" void kernel_launch(void* const* d_in, const int* in_sizes, int n_in,
                              void* d_out, int out_size) {
    const float* x     = (const float*)d_in[0];
    const float* gamma = (const float*)d_in[1];
    const float* beta  = (const float*)d_in[2];
    const float* wq    = (const float*)d_in[3];
    const float* bq    = (const float*)d_in[4];
    const float* wk    = (const float*)d_in[5];
    const float* bk    = (const float*)d_in[6];
    const float* wv    = (const float*)d_in[7];
    const float* bv    = (const float*)d_in[8];
    const float* wo    = (const float*)d_in[9];
    const float* bo    = (const float*)d_in[10];
    float* y = (float*)d_out;

    gn_stats<<<NG, 256>>>(x);
    gn_apply_t<<<dim3(S_TOT / 32, C_DIM / 32), dim3(32, 8)>>>(x, gamma, beta);

    // QKV: M=16384 tokens, N=512 channels
    k_qkv<<<dim3(S_TOT / 128, C_DIM / 128, 3), 256>>>(wq, bq, wk, bk, wv, bv);

    v_transpose<<<dim3(HW / 32, C_DIM / 32, T_FR), dim3(32, 8)>>>();

    const float scale = 0.044194173824159216f;  // 512^-0.5
    k_qk<<<dim3(HW / 128, HW / 128, T_FR), 256>>>(scale);

    softmax_rows<<<S_TOT, 256>>>();

    k_pv<<<dim3(HW / 128, C_DIM / 128, T_FR), 256>>>();

    k_out<<<dim3(C_DIM / 128, S_TOT / 128), 256>>>(wo, bo, x, y);
}

// round 5
// speedup vs baseline: 3.8350x; 1.2743x over previous
#include <cuda_runtime.h>
#include <math.h>

// Problem constants (b=1, c=512, t=16, h=w=32)
#define C_DIM 512
#define T_FR 16
#define HW 1024          // h*w tokens per frame
#define S_TOT 16384      // t*h*w
#define NG 32            // groups
#define CPG 16           // channels per group

// ---------------- scratch (device globals; no allocation allowed) ----------
__device__ __align__(16) float g_hn[S_TOT * C_DIM];        // token-major [s][c]
__device__ __align__(16) float g_q [S_TOT * C_DIM];        // [s][c]
__device__ __align__(16) float g_k [S_TOT * C_DIM];        // [s][c]
__device__ __align__(16) float g_v [S_TOT * C_DIM];        // [s][c]
__device__ __align__(16) float g_vt[T_FR * C_DIM * HW];    // [f][c][j]
__device__ __align__(16) float g_p [T_FR * HW * HW];       // [f][i][j]
__device__ __align__(16) float g_ao[S_TOT * C_DIM];        // [s][c]
__device__ float g_part[NG * 8 * 2];                       // partial GN sums
__device__ float g_mean[NG];
__device__ float g_rstd[NG];

// ---------------- GroupNorm statistics (two-phase) --------------------------
__global__ void gn_stats1(const float* __restrict__ x) {
    const int g = blockIdx.x;
    const int chunk = blockIdx.y;
    const int n_chunk = (CPG * S_TOT) / 8;          // 32768 floats
    const float* xp = x + (size_t)g * CPG * S_TOT + (size_t)chunk * n_chunk;
    float s = 0.f, ss = 0.f;
    for (int i = threadIdx.x; i < n_chunk / 4; i += 256) {
        float4 v = reinterpret_cast<const float4*>(xp)[i];
        s  += v.x + v.y + v.z + v.w;
        ss += v.x * v.x + v.y * v.y + v.z * v.z + v.w * v.w;
    }
    // warp reduce
    #pragma unroll
    for (int o = 16; o > 0; o >>= 1) {
        s  += __shfl_xor_sync(0xffffffffu, s, o);
        ss += __shfl_xor_sync(0xffffffffu, ss, o);
    }
    __shared__ float rs[8], rss[8];
    if ((threadIdx.x & 31) == 0) { rs[threadIdx.x >> 5] = s; rss[threadIdx.x >> 5] = ss; }
    __syncthreads();
    if (threadIdx.x == 0) {
        float ts = 0.f, tss = 0.f;
        #pragma unroll
        for (int i = 0; i < 8; i++) { ts += rs[i]; tss += rss[i]; }
        g_part[(g * 8 + chunk) * 2 + 0] = ts;
        g_part[(g * 8 + chunk) * 2 + 1] = tss;
    }
}

__global__ void gn_stats2() {
    int g = threadIdx.x;
    if (g >= NG) return;
    float s = 0.f, ss = 0.f;
    #pragma unroll
    for (int i = 0; i < 8; i++) {
        s  += g_part[(g * 8 + i) * 2 + 0];
        ss += g_part[(g * 8 + i) * 2 + 1];
    }
    const float inv_n = 1.0f / (float)(CPG * S_TOT);
    float m = s * inv_n;
    float var = ss * inv_n - m * m;
    g_mean[g] = m;
    g_rstd[g] = rsqrtf(var + 1e-6f);
}

// ---------------- GroupNorm apply + transpose to token-major ---------------
__global__ void gn_apply_t(const float* __restrict__ x,
                           const float* __restrict__ gamma,
                           const float* __restrict__ beta) {
    __shared__ float tile[32][33];
    const int s0 = blockIdx.x * 32;
    const int c0 = blockIdx.y * 32;
    const int tx = threadIdx.x, ty = threadIdx.y;
    #pragma unroll
    for (int j = 0; j < 4; j++) {
        int cl = ty + j * 8;
        tile[cl][tx] = x[(size_t)(c0 + cl) * S_TOT + s0 + tx];
    }
    __syncthreads();
    int c = c0 + tx;
    int g = c >> 4;
    float m = g_mean[g], r = g_rstd[g];
    float ga = gamma[c], be = beta[c];
    #pragma unroll
    for (int j = 0; j < 4; j++) {
        int sl = ty + j * 8;
        g_hn[(size_t)(s0 + sl) * C_DIM + c] = (tile[tx][sl] - m) * r * ga + be;
    }
}

// ---------------- per-frame V transpose: [s][c] -> [f][c][j] ----------------
__global__ void v_transpose() {
    __shared__ float tile[32][33];
    const int f  = blockIdx.z;
    const int j0 = blockIdx.x * 32;
    const int c0 = blockIdx.y * 32;
    const int tx = threadIdx.x, ty = threadIdx.y;
    #pragma unroll
    for (int i = 0; i < 4; i++) {
        int jl = ty + i * 8;
        tile[jl][tx] = g_v[(size_t)(f * HW + j0 + jl) * C_DIM + c0 + tx];
    }
    __syncthreads();
    #pragma unroll
    for (int i = 0; i < 4; i++) {
        int cl = ty + i * 8;
        g_vt[(size_t)(f * C_DIM + c0 + cl) * HW + j0 + tx] = tile[tx][cl];
    }
}

// ---------------- tf32 tensor-core GEMM core (cp.async 2-stage) --------------
// out[m][n] = sum_k A[m][k] * B[n][k]  (both K-contiguous, "NT")
// Block tile 128x128, BK=16, 256 threads = 8 warps (2x4), warp tile 64x32.
// fp32 fed to mma.tf32 directly (HW uses upper 19 bits == RZ truncation).

#define BKP 20   // 16 + 4 padding floats (row stride 80B, 16B-aligned)

__device__ __forceinline__ void cp16(float* smem, const float* gmem) {
    unsigned saddr = (unsigned)__cvta_generic_to_shared(smem);
    asm volatile("cp.async.cg.shared.global [%0], [%1], 16;\n" :: "r"(saddr), "l"(gmem));
}
__device__ __forceinline__ void cp_commit() {
    asm volatile("cp.async.commit_group;\n");
}
__device__ __forceinline__ void cp_wait0() {
    asm volatile("cp.async.wait_group 0;\n");
}

__device__ __forceinline__ void mma_tf32(float c[4],
                                         unsigned a0, unsigned a1, unsigned a2, unsigned a3,
                                         unsigned b0, unsigned b1) {
    asm volatile(
        "mma.sync.aligned.m16n8k8.row.col.f32.tf32.tf32.f32 "
        "{%0,%1,%2,%3},{%4,%5,%6,%7},{%8,%9},{%0,%1,%2,%3};\n"
        : "+f"(c[0]), "+f"(c[1]), "+f"(c[2]), "+f"(c[3])
        : "r"(a0), "r"(a1), "r"(a2), "r"(a3), "r"(b0), "r"(b1));
}

__device__ __forceinline__ void gemm_core(const float* __restrict__ A,
                                          const float* __restrict__ B,
                                          int lda, int ldb, int K,
                                          float acc[4][4][4]) {
    __shared__ float As[2][128 * BKP];
    __shared__ float Bs[2][128 * BKP];
    const int tid  = threadIdx.x;
    const int lane = tid & 31;
    const int warp = tid >> 5;
    const int g    = lane >> 2;
    const int tig  = lane & 3;
    const int wm   = (warp >> 2) * 64;
    const int wn   = (warp & 3) * 32;

    const int row_a = tid >> 2;          // 0..63  (also loads row_a+64)
    const int kq    = (tid & 3) * 4;

    const float* Ap0 = A + (size_t)row_a * lda + kq;
    const float* Ap1 = A + (size_t)(row_a + 64) * lda + kq;
    const float* Bp0 = B + (size_t)row_a * ldb + kq;
    const float* Bp1 = B + (size_t)(row_a + 64) * ldb + kq;
    float* sa0 = &As[0][row_a * BKP + kq];
    float* sa1 = &As[0][(row_a + 64) * BKP + kq];
    float* sb0 = &Bs[0][row_a * BKP + kq];
    float* sb1 = &Bs[0][(row_a + 64) * BKP + kq];
    const int stage_off = 128 * BKP;

    // prologue: stage 0
    cp16(sa0, Ap0); cp16(sa1, Ap1);
    cp16(sb0, Bp0); cp16(sb1, Bp1);
    cp_commit();

    const int n_iter = K >> 4;
    for (int it = 0; it < n_iter; it++) {
        cp_wait0();
        __syncthreads();

        // prefetch next tile into the other stage (overlaps with mma below)
        if (it + 1 < n_iter) {
            int k0 = (it + 1) << 4;
            int st = (it + 1) & 1;
            cp16(sa0 + st * stage_off, Ap0 + k0);
            cp16(sa1 + st * stage_off, Ap1 + k0);
            cp16(sb0 + st * stage_off, Bp0 + k0);
            cp16(sb1 + st * stage_off, Bp1 + k0);
            cp_commit();
        } else {
            cp_commit();   // keep group count uniform
        }

        const unsigned* sA = reinterpret_cast<const unsigned*>(&As[it & 1][0]);
        const unsigned* sB = reinterpret_cast<const unsigned*>(&Bs[it & 1][0]);
        #pragma unroll
        for (int k8 = 0; k8 < 2; k8++) {
            unsigned af[4][4], bf[4][2];
            #pragma unroll
            for (int mi = 0; mi < 4; mi++) {
                const unsigned* p = &sA[(wm + mi * 16 + g) * BKP + k8 * 8 + tig];
                af[mi][0] = p[0];
                af[mi][1] = p[8 * BKP];
                af[mi][2] = p[4];
                af[mi][3] = p[8 * BKP + 4];
            }
            #pragma unroll
            for (int ni = 0; ni < 4; ni++) {
                const unsigned* p = &sB[(wn + ni * 8 + g) * BKP + k8 * 8 + tig];
                bf[ni][0] = p[0];
                bf[ni][1] = p[4];
            }
            #pragma unroll
            for (int mi = 0; mi < 4; mi++)
                #pragma unroll
                for (int ni = 0; ni < 4; ni++)
                    mma_tf32(acc[mi][ni],
                             af[mi][0], af[mi][1], af[mi][2], af[mi][3],
                             bf[ni][0], bf[ni][1]);
        }
        __syncthreads();
    }
}

// ---------------- GEMM 1: QKV projections -----------------------------------
__global__ void __launch_bounds__(256, 2) k_qkv(
        const float* __restrict__ wq, const float* __restrict__ bq,
        const float* __restrict__ wk, const float* __restrict__ bk,
        const float* __restrict__ wv, const float* __restrict__ bv) {
    const float* W; const float* Bi; float* out;
    if (blockIdx.z == 0)      { W = wq; Bi = bq; out = g_q; }
    else if (blockIdx.z == 1) { W = wk; Bi = bk; out = g_k; }
    else                      { W = wv; Bi = bv; out = g_v; }
    const int m0 = blockIdx.x * 128;   // token
    const int n0 = blockIdx.y * 128;   // out channel
    float acc[4][4][4] = {};
    gemm_core(g_hn + (size_t)m0 * C_DIM, W + (size_t)n0 * C_DIM, C_DIM, C_DIM, C_DIM, acc);

    const int tid = threadIdx.x, lane = tid & 31, warp = tid >> 5;
    const int g = lane >> 2, tig = lane & 3;
    const int wm = (warp >> 2) * 64, wn = (warp & 3) * 32;
    #pragma unroll
    for (int mi = 0; mi < 4; mi++) {
        int r0 = m0 + wm + mi * 16 + g;
        #pragma unroll
        for (int ni = 0; ni < 4; ni++) {
            int c = n0 + wn + ni * 8 + 2 * tig;
            float b0v = Bi[c], b1v = Bi[c + 1];
            out[(size_t)r0 * C_DIM + c]           = acc[mi][ni][0] + b0v;
            out[(size_t)r0 * C_DIM + c + 1]       = acc[mi][ni][1] + b1v;
            out[(size_t)(r0 + 8) * C_DIM + c]     = acc[mi][ni][2] + b0v;
            out[(size_t)(r0 + 8) * C_DIM + c + 1] = acc[mi][ni][3] + b1v;
        }
    }
}

// ---------------- GEMM 2: S = scale * Q K^T (batched frames) ----------------
__global__ void __launch_bounds__(256, 2) k_qk(float scale) {
    const int f  = blockIdx.z;
    const int m0 = blockIdx.x * 128;
    const int n0 = blockIdx.y * 128;
    const float* Q  = g_q + (size_t)f * HW * C_DIM + (size_t)m0 * C_DIM;
    const float* Km = g_k + (size_t)f * HW * C_DIM + (size_t)n0 * C_DIM;
    float* P = g_p + (size_t)f * HW * HW;
    float acc[4][4][4] = {};
    gemm_core(Q, Km, C_DIM, C_DIM, C_DIM, acc);

    const int tid = threadIdx.x, lane = tid & 31, warp = tid >> 5;
    const int g = lane >> 2, tig = lane & 3;
    const int wm = (warp >> 2) * 64, wn = (warp & 3) * 32;
    #pragma unroll
    for (int mi = 0; mi < 4; mi++) {
        int r0 = m0 + wm + mi * 16 + g;
        #pragma unroll
        for (int ni = 0; ni < 4; ni++) {
            int c = n0 + wn + ni * 8 + 2 * tig;
            P[(size_t)r0 * HW + c]           = acc[mi][ni][0] * scale;
            P[(size_t)r0 * HW + c + 1]       = acc[mi][ni][1] * scale;
            P[(size_t)(r0 + 8) * HW + c]     = acc[mi][ni][2] * scale;
            P[(size_t)(r0 + 8) * HW + c + 1] = acc[mi][ni][3] * scale;
        }
    }
}

// ---------------- row softmax: single pass, float4 + shuffle ----------------
__global__ void softmax_rows() {
    const int row = blockIdx.x;
    float4* p4 = reinterpret_cast<float4*>(g_p + (size_t)row * HW);
    const int tid  = threadIdx.x;
    const int lane = tid & 31;
    const int wid  = tid >> 5;
    __shared__ float red[8];

    float4 v = p4[tid];
    float mx = fmaxf(fmaxf(v.x, v.y), fmaxf(v.z, v.w));
    #pragma unroll
    for (int o = 16; o > 0; o >>= 1) mx = fmaxf(mx, __shfl_xor_sync(0xffffffffu, mx, o));
    if (lane == 0) red[wid] = mx;
    __syncthreads();
    mx = red[lane & 7];
    #pragma unroll
    for (int o = 4; o > 0; o >>= 1) mx = fmaxf(mx, __shfl_xor_sync(0xffffffffu, mx, o));

    v.x = __expf(v.x - mx); v.y = __expf(v.y - mx);
    v.z = __expf(v.z - mx); v.w = __expf(v.w - mx);
    float s = v.x + v.y + v.z + v.w;
    #pragma unroll
    for (int o = 16; o > 0; o >>= 1) s += __shfl_xor_sync(0xffffffffu, s, o);
    __syncthreads();
    if (lane == 0) red[wid] = s;
    __syncthreads();
    s = red[lane & 7];
    #pragma unroll
    for (int o = 4; o > 0; o >>= 1) s += __shfl_xor_sync(0xffffffffu, s, o);

    float inv = __frcp_rn(s);
    v.x *= inv; v.y *= inv; v.z *= inv; v.w *= inv;
    p4[tid] = v;
}

// ---------------- GEMM 3: O = P V (batched frames) ---------------------------
__global__ void __launch_bounds__(256, 2) k_pv() {
    const int f  = blockIdx.z;
    const int m0 = blockIdx.x * 128;   // query token
    const int n0 = blockIdx.y * 128;   // channel
    const float* P  = g_p  + (size_t)f * HW * HW + (size_t)m0 * HW;
    const float* Vt = g_vt + (size_t)f * C_DIM * HW + (size_t)n0 * HW;
    float acc[4][4][4] = {};
    gemm_core(P, Vt, HW, HW, HW, acc);

    const int tid = threadIdx.x, lane = tid & 31, warp = tid >> 5;
    const int g = lane >> 2, tig = lane & 3;
    const int wm = (warp >> 2) * 64, wn = (warp & 3) * 32;
    float* O = g_ao + (size_t)f * HW * C_DIM;
    #pragma unroll
    for (int mi = 0; mi < 4; mi++) {
        int r0 = m0 + wm + mi * 16 + g;
        #pragma unroll
        for (int ni = 0; ni < 4; ni++) {
            int c = n0 + wn + ni * 8 + 2 * tig;
            O[(size_t)r0 * C_DIM + c]           = acc[mi][ni][0];
            O[(size_t)r0 * C_DIM + c + 1]       = acc[mi][ni][1];
            O[(size_t)(r0 + 8) * C_DIM + c]     = acc[mi][ni][2];
            O[(size_t)(r0 + 8) * C_DIM + c + 1] = acc[mi][ni][3];
        }
    }
}

// ---------------- GEMM 4: out proj + bias + residual ------------------------
__global__ void __launch_bounds__(256, 2) k_out(
        const float* __restrict__ wo, const float* __restrict__ bo,
        const float* __restrict__ x, float* __restrict__ y) {
    const int m0 = blockIdx.x * 128;   // out channel
    const int n0 = blockIdx.y * 128;   // spatial position
    float acc[4][4][4] = {};
    gemm_core(wo + (size_t)m0 * C_DIM, g_ao + (size_t)n0 * C_DIM, C_DIM, C_DIM, C_DIM, acc);

    const int tid = threadIdx.x, lane = tid & 31, warp = tid >> 5;
    const int g = lane >> 2, tig = lane & 3;
    const int wm = (warp >> 2) * 64, wn = (warp & 3) * 32;
    #pragma unroll
    for (int mi = 0; mi < 4; mi++) {
        int r0 = m0 + wm + mi * 16 + g;
        float bo0 = bo[r0], bo1 = bo[r0 + 8];
        #pragma unroll
        for (int ni = 0; ni < 4; ni++) {
            int c = n0 + wn + ni * 8 + 2 * tig;
            size_t i00 = (size_t)r0 * S_TOT + c;
            size_t i10 = (size_t)(r0 + 8) * S_TOT + c;
            y[i00]     = acc[mi][ni][0] + bo0 + x[i00];
            y[i00 + 1] = acc[mi][ni][1] + bo0 + x[i00 + 1];
            y[i10]     = acc[mi][ni][2] + bo1 + x[i10];
            y[i10 + 1] = acc[mi][ni][3] + bo1 + x[i10 + 1];
        }
    }
}

// ---------------- launch ------------------------------------------------------
extern "C" void kernel_launch(void* const* d_in, const int* in_sizes, int n_in,
                              void* d_out, int out_size) {
    const float* x     = (const float*)d_in[0];
    const float* gamma = (const float*)d_in[1];
    const float* beta  = (const float*)d_in[2];
    const float* wq    = (const float*)d_in[3];
    const float* bq    = (const float*)d_in[4];
    const float* wk    = (const float*)d_in[5];
    const float* bk    = (const float*)d_in[6];
    const float* wv    = (const float*)d_in[7];
    const float* bv    = (const float*)d_in[8];
    const float* wo    = (const float*)d_in[9];
    const float* bo    = (const float*)d_in[10];
    float* y = (float*)d_out;

    gn_stats1<<<dim3(NG, 8), 256>>>(x);
    gn_stats2<<<1, 32>>>();
    gn_apply_t<<<dim3(S_TOT / 32, C_DIM / 32), dim3(32, 8)>>>(x, gamma, beta);

    k_qkv<<<dim3(S_TOT / 128, C_DIM / 128, 3), 256>>>(wq, bq, wk, bk, wv, bv);

    v_transpose<<<dim3(HW / 32, C_DIM / 32, T_FR), dim3(32, 8)>>>();

    const float scale = 0.044194173824159216f;  // 512^-0.5
    k_qk<<<dim3(HW / 128, HW / 128, T_FR), 256>>>(scale);

    softmax_rows<<<S_TOT, 256>>>();

    k_pv<<<dim3(HW / 128, C_DIM / 128, T_FR), 256>>>();

    k_out<<<dim3(C_DIM / 128, S_TOT / 128), 256>>>(wo, bo, x, y);
}

// round 7
// speedup vs baseline: 4.7174x; 1.2301x over previous
#include <cuda_runtime.h>
#include <math.h>

// Problem constants (b=1, c=512, t=16, h=w=32)
#define C_DIM 512
#define T_FR 16
#define HW 1024          // h*w tokens per frame
#define S_TOT 16384      // t*h*w
#define NG 32            // groups
#define CPG 16           // channels per group

// ---------------- scratch (device globals; no allocation allowed) ----------
__device__ __align__(16) float g_hn[S_TOT * C_DIM];        // token-major [s][c]
__device__ __align__(16) float g_q [S_TOT * C_DIM];        // [s][c]
__device__ __align__(16) float g_k [S_TOT * C_DIM];        // [s][c]
__device__ __align__(16) float g_v [S_TOT * C_DIM];        // [s][c]
__device__ __align__(16) float g_vt[T_FR * C_DIM * HW];    // [f][c][j]
__device__ __align__(16) float g_p [T_FR * HW * HW];       // [f][i][j]
__device__ __align__(16) float g_ao[S_TOT * C_DIM];        // [s][c]
__device__ float g_part[NG * 8 * 2];                       // partial GN sums
__device__ float g_mean[NG];
__device__ float g_rstd[NG];

// ---------------- GroupNorm statistics (two-phase) --------------------------
__global__ void gn_stats1(const float* __restrict__ x) {
    const int g = blockIdx.x;
    const int chunk = blockIdx.y;
    const int n_chunk = (CPG * S_TOT) / 8;          // 32768 floats
    const float* xp = x + (size_t)g * CPG * S_TOT + (size_t)chunk * n_chunk;
    float s = 0.f, ss = 0.f;
    for (int i = threadIdx.x; i < n_chunk / 4; i += 256) {
        float4 v = reinterpret_cast<const float4*>(xp)[i];
        s  += v.x + v.y + v.z + v.w;
        ss += v.x * v.x + v.y * v.y + v.z * v.z + v.w * v.w;
    }
    #pragma unroll
    for (int o = 16; o > 0; o >>= 1) {
        s  += __shfl_xor_sync(0xffffffffu, s, o);
        ss += __shfl_xor_sync(0xffffffffu, ss, o);
    }
    __shared__ float rs[8], rss[8];
    if ((threadIdx.x & 31) == 0) { rs[threadIdx.x >> 5] = s; rss[threadIdx.x >> 5] = ss; }
    __syncthreads();
    if (threadIdx.x == 0) {
        float ts = 0.f, tss = 0.f;
        #pragma unroll
        for (int i = 0; i < 8; i++) { ts += rs[i]; tss += rss[i]; }
        g_part[(g * 8 + chunk) * 2 + 0] = ts;
        g_part[(g * 8 + chunk) * 2 + 1] = tss;
    }
}

__global__ void gn_stats2() {
    int g = threadIdx.x;
    if (g >= NG) return;
    float s = 0.f, ss = 0.f;
    #pragma unroll
    for (int i = 0; i < 8; i++) {
        s  += g_part[(g * 8 + i) * 2 + 0];
        ss += g_part[(g * 8 + i) * 2 + 1];
    }
    const float inv_n = 1.0f / (float)(CPG * S_TOT);
    float m = s * inv_n;
    float var = ss * inv_n - m * m;
    g_mean[g] = m;
    g_rstd[g] = rsqrtf(var + 1e-6f);
}

// ---------------- GroupNorm apply + transpose to token-major ---------------
__global__ void gn_apply_t(const float* __restrict__ x,
                           const float* __restrict__ gamma,
                           const float* __restrict__ beta) {
    __shared__ float tile[32][33];
    const int s0 = blockIdx.x * 32;
    const int c0 = blockIdx.y * 32;
    const int tx = threadIdx.x, ty = threadIdx.y;
    #pragma unroll
    for (int j = 0; j < 4; j++) {
        int cl = ty + j * 8;
        tile[cl][tx] = x[(size_t)(c0 + cl) * S_TOT + s0 + tx];
    }
    __syncthreads();
    int c = c0 + tx;
    int g = c >> 4;
    float m = g_mean[g], r = g_rstd[g];
    float ga = gamma[c], be = beta[c];
    #pragma unroll
    for (int j = 0; j < 4; j++) {
        int sl = ty + j * 8;
        g_hn[(size_t)(s0 + sl) * C_DIM + c] = (tile[tx][sl] - m) * r * ga + be;
    }
}

// ---------------- per-frame V transpose: [s][c] -> [f][c][j] ----------------
__global__ void v_transpose() {
    __shared__ float tile[32][33];
    const int f  = blockIdx.z;
    const int j0 = blockIdx.x * 32;
    const int c0 = blockIdx.y * 32;
    const int tx = threadIdx.x, ty = threadIdx.y;
    #pragma unroll
    for (int i = 0; i < 4; i++) {
        int jl = ty + i * 8;
        tile[jl][tx] = g_v[(size_t)(f * HW + j0 + jl) * C_DIM + c0 + tx];
    }
    __syncthreads();
    #pragma unroll
    for (int i = 0; i < 4; i++) {
        int cl = ty + i * 8;
        g_vt[(size_t)(f * C_DIM + c0 + cl) * HW + j0 + tx] = tile[tx][cl];
    }
}

// ---------------- tf32 tensor-core GEMM core ---------------------------------
// out[m][n] = sum_k A[m][k] * B[n][k]  (both K-contiguous, "NT")
// Block tile 128x128, BK=16, 256 threads = 8 warps (2x4), warp tile 64x32.
// 3-stage cp.async pipeline, ldmatrix fragment loads, fp32 fed to mma.tf32.

#define BKP 20                     // 16 + 4 padding floats (80B row stride)
#define STAGE_F (128 * BKP)        // floats per stage per matrix
#define N_STAGE 3

__device__ __forceinline__ void cp16(float* smem, const float* gmem) {
    unsigned saddr = (unsigned)__cvta_generic_to_shared(smem);
    asm volatile("cp.async.cg.shared.global [%0], [%1], 16;\n" :: "r"(saddr), "l"(gmem));
}
__device__ __forceinline__ void cp_commit() {
    asm volatile("cp.async.commit_group;\n");
}
__device__ __forceinline__ void cp_wait1() {
    asm volatile("cp.async.wait_group 1;\n");
}

__device__ __forceinline__ void ldsm_x4(unsigned& r0, unsigned& r1, unsigned& r2, unsigned& r3,
                                        unsigned addr) {
    asm volatile("ldmatrix.sync.aligned.m8n8.x4.shared.b16 {%0,%1,%2,%3}, [%4];"
                 : "=r"(r0), "=r"(r1), "=r"(r2), "=r"(r3) : "r"(addr));
}
__device__ __forceinline__ void ldsm_x2(unsigned& r0, unsigned& r1, unsigned addr) {
    asm volatile("ldmatrix.sync.aligned.m8n8.x2.shared.b16 {%0,%1}, [%2];"
                 : "=r"(r0), "=r"(r1) : "r"(addr));
}

__device__ __forceinline__ void mma_tf32(float c[4],
                                         unsigned a0, unsigned a1, unsigned a2, unsigned a3,
                                         unsigned b0, unsigned b1) {
    asm volatile(
        "mma.sync.aligned.m16n8k8.row.col.f32.tf32.tf32.f32 "
        "{%0,%1,%2,%3},{%4,%5,%6,%7},{%8,%9},{%0,%1,%2,%3};\n"
        : "+f"(c[0]), "+f"(c[1]), "+f"(c[2]), "+f"(c[3])
        : "r"(a0), "r"(a1), "r"(a2), "r"(a3), "r"(b0), "r"(b1));
}

__device__ __forceinline__ void gemm_core(const float* __restrict__ A,
                                          const float* __restrict__ B,
                                          int lda, int ldb, int K,
                                          float acc[4][4][4]) {
    __shared__ float As[N_STAGE * STAGE_F];
    __shared__ float Bs[N_STAGE * STAGE_F];
    const int tid  = threadIdx.x;
    const int lane = tid & 31;
    const int warp = tid >> 5;
    const int wm   = (warp >> 2) * 64;
    const int wn   = (warp & 3) * 32;

    // cp.async mapping: each thread stages 16B for rows (tid>>2) and (tid>>2)+64
    const int row_a = tid >> 2;
    const int kq    = (tid & 3) * 4;
    const float* Ap0 = A + (size_t)row_a * lda + kq;
    const float* Ap1 = A + (size_t)(row_a + 64) * lda + kq;
    const float* Bp0 = B + (size_t)row_a * ldb + kq;
    const float* Bp1 = B + (size_t)(row_a + 64) * ldb + kq;
    float* sa0 = &As[row_a * BKP + kq];
    float* sa1 = &As[(row_a + 64) * BKP + kq];
    float* sb0 = &Bs[row_a * BKP + kq];
    float* sb1 = &Bs[(row_a + 64) * BKP + kq];

    // ldmatrix per-lane row pointers
    const unsigned asBase = (unsigned)__cvta_generic_to_shared(As);
    const unsigned bsBase = (unsigned)__cvta_generic_to_shared(Bs);
    const int a_row  = lane & 15;            // rows 0-15 of the 16-row fragment
    const int a_kadd = (lane >> 4) * 4;      // lanes 16-31 -> k+4 matrices
    const int b_row  = lane & 7;
    const int b_kadd = ((lane >> 3) & 1) * 4;
    // lane-invariant-per-(mi,k8) bases
    const unsigned aLane = (unsigned)(((wm + a_row) * BKP + a_kadd) * 4);
    const unsigned bLane = (unsigned)(((wn + b_row) * BKP + b_kadd) * 4);

    const int n_iter = K >> 4;

    // prologue: tiles 0,1
    #pragma unroll
    for (int s = 0; s < 2; s++) {
        int k0 = s << 4;
        cp16(sa0 + s * STAGE_F, Ap0 + k0);
        cp16(sa1 + s * STAGE_F, Ap1 + k0);
        cp16(sb0 + s * STAGE_F, Bp0 + k0);
        cp16(sb1 + s * STAGE_F, Bp1 + k0);
        cp_commit();
    }

    int st = 0, pst = 2;
    for (int it = 0; it < n_iter; it++) {
        cp_wait1();
        __syncthreads();

        // prefetch tile it+2 into stage pst (overlaps with mma below)
        if (it + 2 < n_iter) {
            int k0 = (it + 2) << 4;
            cp16(sa0 + pst * STAGE_F, Ap0 + k0);
            cp16(sa1 + pst * STAGE_F, Ap1 + k0);
            cp16(sb0 + pst * STAGE_F, Bp0 + k0);
            cp16(sb1 + pst * STAGE_F, Bp1 + k0);
        }
        cp_commit();   // always commit to keep wait_group invariant

        const unsigned aStage = asBase + (unsigned)(st * STAGE_F * 4) + aLane;
        const unsigned bStage = bsBase + (unsigned)(st * STAGE_F * 4) + bLane;
        #pragma unroll
        for (int k8 = 0; k8 < 2; k8++) {
            unsigned af[4][4], bf[4][2];
            #pragma unroll
            for (int mi = 0; mi < 4; mi++)
                ldsm_x4(af[mi][0], af[mi][1], af[mi][2], af[mi][3],
                        aStage + (unsigned)((mi * 16 * BKP + k8 * 8) * 4));
            #pragma unroll
            for (int ni = 0; ni < 4; ni++)
                ldsm_x2(bf[ni][0], bf[ni][1],
                        bStage + (unsigned)((ni * 8 * BKP + k8 * 8) * 4));
            #pragma unroll
            for (int mi = 0; mi < 4; mi++)
                #pragma unroll
                for (int ni = 0; ni < 4; ni++)
                    mma_tf32(acc[mi][ni],
                             af[mi][0], af[mi][1], af[mi][2], af[mi][3],
                             bf[ni][0], bf[ni][1]);
        }
        st  = (st  == N_STAGE - 1) ? 0 : st + 1;
        pst = (pst == N_STAGE - 1) ? 0 : pst + 1;
    }
}

// Epilogue index helpers: r0 = m0+wm+mi*16+g ; r1 = r0+8 ; c = n0+wn+ni*8+2*tig

// ---------------- GEMM 1: QKV projections -----------------------------------
__global__ void __launch_bounds__(256, 2) k_qkv(
        const float* __restrict__ wq, const float* __restrict__ bq,
        const float* __restrict__ wk, const float* __restrict__ bk,
        const float* __restrict__ wv, const float* __restrict__ bv) {
    const float* W; const float* Bi; float* out;
    if (blockIdx.z == 0)      { W = wq; Bi = bq; out = g_q; }
    else if (blockIdx.z == 1) { W = wk; Bi = bk; out = g_k; }
    else                      { W = wv; Bi = bv; out = g_v; }
    const int m0 = blockIdx.x * 128;   // token
    const int n0 = blockIdx.y * 128;   // out channel
    float acc[4][4][4] = {};
    gemm_core(g_hn + (size_t)m0 * C_DIM, W + (size_t)n0 * C_DIM, C_DIM, C_DIM, C_DIM, acc);

    const int tid = threadIdx.x, lane = tid & 31, warp = tid >> 5;
    const int g = lane >> 2, tig = lane & 3;
    const int wm = (warp >> 2) * 64, wn = (warp & 3) * 32;
    #pragma unroll
    for (int mi = 0; mi < 4; mi++) {
        int r0 = m0 + wm + mi * 16 + g;
        #pragma unroll
        for (int ni = 0; ni < 4; ni++) {
            int c = n0 + wn + ni * 8 + 2 * tig;
            float b0v = Bi[c], b1v = Bi[c + 1];
            *reinterpret_cast<float2*>(&out[(size_t)r0 * C_DIM + c]) =
                make_float2(acc[mi][ni][0] + b0v, acc[mi][ni][1] + b1v);
            *reinterpret_cast<float2*>(&out[(size_t)(r0 + 8) * C_DIM + c]) =
                make_float2(acc[mi][ni][2] + b0v, acc[mi][ni][3] + b1v);
        }
    }
}

// ---------------- GEMM 2: S = scale * Q K^T (batched frames) ----------------
__global__ void __launch_bounds__(256, 2) k_qk(float scale) {
    const int f  = blockIdx.z;
    const int m0 = blockIdx.x * 128;
    const int n0 = blockIdx.y * 128;
    const float* Q  = g_q + (size_t)f * HW * C_DIM + (size_t)m0 * C_DIM;
    const float* Km = g_k + (size_t)f * HW * C_DIM + (size_t)n0 * C_DIM;
    float* P = g_p + (size_t)f * HW * HW;
    float acc[4][4][4] = {};
    gemm_core(Q, Km, C_DIM, C_DIM, C_DIM, acc);

    const int tid = threadIdx.x, lane = tid & 31, warp = tid >> 5;
    const int g = lane >> 2, tig = lane & 3;
    const int wm = (warp >> 2) * 64, wn = (warp & 3) * 32;
    #pragma unroll
    for (int mi = 0; mi < 4; mi++) {
        int r0 = m0 + wm + mi * 16 + g;
        #pragma unroll
        for (int ni = 0; ni < 4; ni++) {
            int c = n0 + wn + ni * 8 + 2 * tig;
            *reinterpret_cast<float2*>(&P[(size_t)r0 * HW + c]) =
                make_float2(acc[mi][ni][0] * scale, acc[mi][ni][1] * scale);
            *reinterpret_cast<float2*>(&P[(size_t)(r0 + 8) * HW + c]) =
                make_float2(acc[mi][ni][2] * scale, acc[mi][ni][3] * scale);
        }
    }
}

// ---------------- row softmax: single pass, float4 + shuffle ----------------
__global__ void softmax_rows() {
    const int row = blockIdx.x;
    float4* p4 = reinterpret_cast<float4*>(g_p + (size_t)row * HW);
    const int tid  = threadIdx.x;
    const int lane = tid & 31;
    const int wid  = tid >> 5;
    __shared__ float red[8];

    float4 v = p4[tid];
    float mx = fmaxf(fmaxf(v.x, v.y), fmaxf(v.z, v.w));
    #pragma unroll
    for (int o = 16; o > 0; o >>= 1) mx = fmaxf(mx, __shfl_xor_sync(0xffffffffu, mx, o));
    if (lane == 0) red[wid] = mx;
    __syncthreads();
    mx = red[lane & 7];
    #pragma unroll
    for (int o = 4; o > 0; o >>= 1) mx = fmaxf(mx, __shfl_xor_sync(0xffffffffu, mx, o));

    v.x = __expf(v.x - mx); v.y = __expf(v.y - mx);
    v.z = __expf(v.z - mx); v.w = __expf(v.w - mx);
    float s = v.x + v.y + v.z + v.w;
    #pragma unroll
    for (int o = 16; o > 0; o >>= 1) s += __shfl_xor_sync(0xffffffffu, s, o);
    __syncthreads();
    if (lane == 0) red[wid] = s;
    __syncthreads();
    s = red[lane & 7];
    #pragma unroll
    for (int o = 4; o > 0; o >>= 1) s += __shfl_xor_sync(0xffffffffu, s, o);

    float inv = __frcp_rn(s);
    v.x *= inv; v.y *= inv; v.z *= inv; v.w *= inv;
    p4[tid] = v;
}

// ---------------- GEMM 3: O = P V (batched frames) ---------------------------
__global__ void __launch_bounds__(256, 2) k_pv() {
    const int f  = blockIdx.z;
    const int m0 = blockIdx.x * 128;   // query token
    const int n0 = blockIdx.y * 128;   // channel
    const float* P  = g_p  + (size_t)f * HW * HW + (size_t)m0 * HW;
    const float* Vt = g_vt + (size_t)f * C_DIM * HW + (size_t)n0 * HW;
    float acc[4][4][4] = {};
    gemm_core(P, Vt, HW, HW, HW, acc);

    const int tid = threadIdx.x, lane = tid & 31, warp = tid >> 5;
    const int g = lane >> 2, tig = lane & 3;
    const int wm = (warp >> 2) * 64, wn = (warp & 3) * 32;
    float* O = g_ao + (size_t)f * HW * C_DIM;
    #pragma unroll
    for (int mi = 0; mi < 4; mi++) {
        int r0 = m0 + wm + mi * 16 + g;
        #pragma unroll
        for (int ni = 0; ni < 4; ni++) {
            int c = n0 + wn + ni * 8 + 2 * tig;
            *reinterpret_cast<float2*>(&O[(size_t)r0 * C_DIM + c]) =
                make_float2(acc[mi][ni][0], acc[mi][ni][1]);
            *reinterpret_cast<float2*>(&O[(size_t)(r0 + 8) * C_DIM + c]) =
                make_float2(acc[mi][ni][2], acc[mi][ni][3]);
        }
    }
}

// ---------------- GEMM 4: out proj + bias + residual ------------------------
__global__ void __launch_bounds__(256, 2) k_out(
        const float* __restrict__ wo, const float* __restrict__ bo,
        const float* __restrict__ x, float* __restrict__ y) {
    const int m0 = blockIdx.x * 128;   // out channel
    const int n0 = blockIdx.y * 128;   // spatial position
    float acc[4][4][4] = {};
    gemm_core(wo + (size_t)m0 * C_DIM, g_ao + (size_t)n0 * C_DIM, C_DIM, C_DIM, C_DIM, acc);

    const int tid = threadIdx.x, lane = tid & 31, warp = tid >> 5;
    const int g = lane >> 2, tig = lane & 3;
    const int wm = (warp >> 2) * 64, wn = (warp & 3) * 32;
    #pragma unroll
    for (int mi = 0; mi < 4; mi++) {
        int r0 = m0 + wm + mi * 16 + g;
        float bo0 = bo[r0], bo1 = bo[r0 + 8];
        #pragma unroll
        for (int ni = 0; ni < 4; ni++) {
            int c = n0 + wn + ni * 8 + 2 * tig;
            size_t i00 = (size_t)r0 * S_TOT + c;
            size_t i10 = (size_t)(r0 + 8) * S_TOT + c;
            float2 x0 = *reinterpret_cast<const float2*>(&x[i00]);
            float2 x1 = *reinterpret_cast<const float2*>(&x[i10]);
            *reinterpret_cast<float2*>(&y[i00]) =
                make_float2(acc[mi][ni][0] + bo0 + x0.x, acc[mi][ni][1] + bo0 + x0.y);
            *reinterpret_cast<float2*>(&y[i10]) =
                make_float2(acc[mi][ni][2] + bo1 + x1.x, acc[mi][ni][3] + bo1 + x1.y);
        }
    }
}

// ---------------- launch ------------------------------------------------------
extern "C" void kernel_launch(void* const* d_in, const int* in_sizes, int n_in,
                              void* d_out, int out_size) {
    const float* x     = (const float*)d_in[0];
    const float* gamma = (const float*)d_in[1];
    const float* beta  = (const float*)d_in[2];
    const float* wq    = (const float*)d_in[3];
    const float* bq    = (const float*)d_in[4];
    const float* wk    = (const float*)d_in[5];
    const float* bk    = (const float*)d_in[6];
    const float* wv    = (const float*)d_in[7];
    const float* bv    = (const float*)d_in[8];
    const float* wo    = (const float*)d_in[9];
    const float* bo    = (const float*)d_in[10];
    float* y = (float*)d_out;

    gn_stats1<<<dim3(NG, 8), 256>>>(x);
    gn_stats2<<<1, 32>>>();
    gn_apply_t<<<dim3(S_TOT / 32, C_DIM / 32), dim3(32, 8)>>>(x, gamma, beta);

    k_qkv<<<dim3(S_TOT / 128, C_DIM / 128, 3), 256>>>(wq, bq, wk, bk, wv, bv);

    v_transpose<<<dim3(HW / 32, C_DIM / 32, T_FR), dim3(32, 8)>>>();

    const float scale = 0.044194173824159216f;  // 512^-0.5
    k_qk<<<dim3(HW / 128, HW / 128, T_FR), 256>>>(scale);

    softmax_rows<<<S_TOT, 256>>>();

    k_pv<<<dim3(HW / 128, C_DIM / 128, T_FR), 256>>>();

    k_out<<<dim3(C_DIM / 128, S_TOT / 128), 256>>>(wo, bo, x, y);
}

// round 8
// speedup vs baseline: 7.7870x; 1.6507x over previous
#include <cuda_runtime.h>
#include <cuda_bf16.h>
#include <math.h>

// Problem constants (b=1, c=512, t=16, h=w=32)
#define C_DIM 512
#define T_FR 16
#define HW 1024          // h*w tokens per frame
#define S_TOT 16384      // t*h*w
#define NG 32            // groups
#define CPG 16           // channels per group

typedef __nv_bfloat16 bf16;
typedef __nv_bfloat162 bf162;

// ---------------- scratch (device globals; no allocation allowed) ----------
__device__ __align__(16) bf16  g_hn[S_TOT * C_DIM];        // token-major [s][c]
__device__ __align__(16) bf16  g_q [S_TOT * C_DIM];        // [s][c]
__device__ __align__(16) bf16  g_k [S_TOT * C_DIM];        // [s][c]
__device__ __align__(16) bf16  g_v [S_TOT * C_DIM];        // [s][c]
__device__ __align__(16) bf16  g_vt[T_FR * C_DIM * HW];    // [f][c][j]
__device__ __align__(16) float g_p [T_FR * HW * HW];       // [f][i][j] fp32 scores
__device__ __align__(16) bf16  g_pb[T_FR * HW * HW];       // bf16 probs
__device__ __align__(16) bf16  g_ao[S_TOT * C_DIM];        // [s][c]
__device__ __align__(16) bf16  g_wq[C_DIM * C_DIM];
__device__ __align__(16) bf16  g_wk[C_DIM * C_DIM];
__device__ __align__(16) bf16  g_wv[C_DIM * C_DIM];
__device__ __align__(16) bf16  g_wo[C_DIM * C_DIM];
__device__ float g_part[NG * 8 * 2];
__device__ float g_mean[NG];
__device__ float g_rstd[NG];

// ---------------- weight fp32 -> bf16 conversion ----------------------------
__global__ void w_convert(const float* __restrict__ w0, const float* __restrict__ w1,
                          const float* __restrict__ w2, const float* __restrict__ w3) {
    const float* src; bf16* dst;
    if (blockIdx.y == 0)      { src = w0; dst = g_wq; }
    else if (blockIdx.y == 1) { src = w1; dst = g_wk; }
    else if (blockIdx.y == 2) { src = w2; dst = g_wv; }
    else                      { src = w3; dst = g_wo; }
    int i = blockIdx.x * 256 + threadIdx.x;   // float4 index, 65536 total
    float4 v = reinterpret_cast<const float4*>(src)[i];
    bf162* d = reinterpret_cast<bf162*>(dst) + i * 2;
    d[0] = __float22bfloat162_rn(make_float2(v.x, v.y));
    d[1] = __float22bfloat162_rn(make_float2(v.z, v.w));
}

// ---------------- GroupNorm statistics (two-phase) --------------------------
__global__ void gn_stats1(const float* __restrict__ x) {
    const int g = blockIdx.x;
    const int chunk = blockIdx.y;
    const int n_chunk = (CPG * S_TOT) / 8;
    const float* xp = x + (size_t)g * CPG * S_TOT + (size_t)chunk * n_chunk;
    float s = 0.f, ss = 0.f;
    for (int i = threadIdx.x; i < n_chunk / 4; i += 256) {
        float4 v = reinterpret_cast<const float4*>(xp)[i];
        s  += v.x + v.y + v.z + v.w;
        ss += v.x * v.x + v.y * v.y + v.z * v.z + v.w * v.w;
    }
    #pragma unroll
    for (int o = 16; o > 0; o >>= 1) {
        s  += __shfl_xor_sync(0xffffffffu, s, o);
        ss += __shfl_xor_sync(0xffffffffu, ss, o);
    }
    __shared__ float rs[8], rss[8];
    if ((threadIdx.x & 31) == 0) { rs[threadIdx.x >> 5] = s; rss[threadIdx.x >> 5] = ss; }
    __syncthreads();
    if (threadIdx.x == 0) {
        float ts = 0.f, tss = 0.f;
        #pragma unroll
        for (int i = 0; i < 8; i++) { ts += rs[i]; tss += rss[i]; }
        g_part[(g * 8 + chunk) * 2 + 0] = ts;
        g_part[(g * 8 + chunk) * 2 + 1] = tss;
    }
}

__global__ void gn_stats2() {
    int g = threadIdx.x;
    if (g >= NG) return;
    float s = 0.f, ss = 0.f;
    #pragma unroll
    for (int i = 0; i < 8; i++) {
        s  += g_part[(g * 8 + i) * 2 + 0];
        ss += g_part[(g * 8 + i) * 2 + 1];
    }
    const float inv_n = 1.0f / (float)(CPG * S_TOT);
    float m = s * inv_n;
    float var = ss * inv_n - m * m;
    g_mean[g] = m;
    g_rstd[g] = rsqrtf(var + 1e-6f);
}

// ---------------- GroupNorm apply + transpose, emit bf16 --------------------
__global__ void gn_apply_t(const float* __restrict__ x,
                           const float* __restrict__ gamma,
                           const float* __restrict__ beta) {
    __shared__ float tile[32][33];
    const int s0 = blockIdx.x * 32;
    const int c0 = blockIdx.y * 32;
    const int tx = threadIdx.x, ty = threadIdx.y;
    #pragma unroll
    for (int j = 0; j < 4; j++) {
        int cl = ty + j * 8;
        tile[cl][tx] = x[(size_t)(c0 + cl) * S_TOT + s0 + tx];
    }
    __syncthreads();
    int c = c0 + tx;
    int g = c >> 4;
    float m = g_mean[g], r = g_rstd[g];
    float ga = gamma[c], be = beta[c];
    #pragma unroll
    for (int j = 0; j < 4; j++) {
        int sl = ty + j * 8;
        g_hn[(size_t)(s0 + sl) * C_DIM + c] =
            __float2bfloat16_rn((tile[tx][sl] - m) * r * ga + be);
    }
}

// ---------------- per-frame V transpose: [s][c] -> [f][c][j] (bf16) ---------
__global__ void v_transpose() {
    __shared__ bf16 tile[32][34];
    const int f  = blockIdx.z;
    const int j0 = blockIdx.x * 32;
    const int c0 = blockIdx.y * 32;
    const int tx = threadIdx.x, ty = threadIdx.y;
    #pragma unroll
    for (int i = 0; i < 4; i++) {
        int jl = ty + i * 8;
        tile[jl][tx] = g_v[(size_t)(f * HW + j0 + jl) * C_DIM + c0 + tx];
    }
    __syncthreads();
    #pragma unroll
    for (int i = 0; i < 4; i++) {
        int cl = ty + i * 8;
        g_vt[(size_t)(f * C_DIM + c0 + cl) * HW + j0 + tx] = tile[tx][cl];
    }
}

// ---------------- bf16 tensor-core GEMM core ---------------------------------
// out[m][n] = sum_k A[m][k] * B[n][k]  (both K-contiguous, "NT", bf16 data)
// Block tile 128x128, BK=32, 256 threads = 8 warps (2x4), warp tile 64x32.
// 3-stage cp.async pipeline, ldmatrix.b16 fragments, mma m16n8k16, fp32 accum.

#define BKH 40                     // 32 + 8 padding halves (80B row stride)
#define STAGE_H (128 * BKH)        // halves per stage per matrix
#define N_STAGE 3

__device__ __forceinline__ void cp16(void* smem, const void* gmem) {
    unsigned saddr = (unsigned)__cvta_generic_to_shared(smem);
    asm volatile("cp.async.cg.shared.global [%0], [%1], 16;\n" :: "r"(saddr), "l"(gmem));
}
__device__ __forceinline__ void cp_commit() {
    asm volatile("cp.async.commit_group;\n");
}
__device__ __forceinline__ void cp_wait1() {
    asm volatile("cp.async.wait_group 1;\n");
}

__device__ __forceinline__ void ldsm_x4(unsigned& r0, unsigned& r1, unsigned& r2, unsigned& r3,
                                        unsigned addr) {
    asm volatile("ldmatrix.sync.aligned.m8n8.x4.shared.b16 {%0,%1,%2,%3}, [%4];"
                 : "=r"(r0), "=r"(r1), "=r"(r2), "=r"(r3) : "r"(addr));
}
__device__ __forceinline__ void ldsm_x2(unsigned& r0, unsigned& r1, unsigned addr) {
    asm volatile("ldmatrix.sync.aligned.m8n8.x2.shared.b16 {%0,%1}, [%2];"
                 : "=r"(r0), "=r"(r1) : "r"(addr));
}

__device__ __forceinline__ void mma_bf16(float c[4],
                                         unsigned a0, unsigned a1, unsigned a2, unsigned a3,
                                         unsigned b0, unsigned b1) {
    asm volatile(
        "mma.sync.aligned.m16n8k16.row.col.f32.bf16.bf16.f32 "
        "{%0,%1,%2,%3},{%4,%5,%6,%7},{%8,%9},{%0,%1,%2,%3};\n"
        : "+f"(c[0]), "+f"(c[1]), "+f"(c[2]), "+f"(c[3])
        : "r"(a0), "r"(a1), "r"(a2), "r"(a3), "r"(b0), "r"(b1));
}

__device__ __forceinline__ void gemm_core(const bf16* __restrict__ A,
                                          const bf16* __restrict__ B,
                                          int lda, int ldb, int K,
                                          float acc[4][4][4]) {
    __shared__ bf16 As[N_STAGE * STAGE_H];
    __shared__ bf16 Bs[N_STAGE * STAGE_H];
    const int tid  = threadIdx.x;
    const int lane = tid & 31;
    const int warp = tid >> 5;
    const int wm   = (warp >> 2) * 64;
    const int wn   = (warp & 3) * 32;

    // cp.async mapping: thread stages 16B (8 halves) for rows tid>>2 and +64
    const int row_a = tid >> 2;
    const int kqh   = (tid & 3) * 8;
    const bf16* Ap0 = A + (size_t)row_a * lda + kqh;
    const bf16* Ap1 = A + (size_t)(row_a + 64) * lda + kqh;
    const bf16* Bp0 = B + (size_t)row_a * ldb + kqh;
    const bf16* Bp1 = B + (size_t)(row_a + 64) * ldb + kqh;
    bf16* sa0 = &As[row_a * BKH + kqh];
    bf16* sa1 = &As[(row_a + 64) * BKH + kqh];
    bf16* sb0 = &Bs[row_a * BKH + kqh];
    bf16* sb1 = &Bs[(row_a + 64) * BKH + kqh];

    // ldmatrix per-lane bases (byte offsets)
    const unsigned asBase = (unsigned)__cvta_generic_to_shared(As);
    const unsigned bsBase = (unsigned)__cvta_generic_to_shared(Bs);
    const unsigned aLane = (unsigned)(((wm + (lane & 15)) * BKH + (lane >> 4) * 8) * 2);
    const unsigned bLane = (unsigned)(((wn + (lane & 7))  * BKH + ((lane >> 3) & 1) * 8) * 2);

    const int n_iter = K >> 5;

    // prologue: tiles 0,1
    #pragma unroll
    for (int s = 0; s < 2; s++) {
        int k0 = s << 5;
        cp16(sa0 + s * STAGE_H, Ap0 + k0);
        cp16(sa1 + s * STAGE_H, Ap1 + k0);
        cp16(sb0 + s * STAGE_H, Bp0 + k0);
        cp16(sb1 + s * STAGE_H, Bp1 + k0);
        cp_commit();
    }

    int st = 0, pst = 2;
    for (int it = 0; it < n_iter; it++) {
        cp_wait1();
        __syncthreads();

        if (it + 2 < n_iter) {
            int k0 = (it + 2) << 5;
            cp16(sa0 + pst * STAGE_H, Ap0 + k0);
            cp16(sa1 + pst * STAGE_H, Ap1 + k0);
            cp16(sb0 + pst * STAGE_H, Bp0 + k0);
            cp16(sb1 + pst * STAGE_H, Bp1 + k0);
        }
        cp_commit();   // keep wait_group invariant

        const unsigned aStage = asBase + (unsigned)(st * STAGE_H * 2) + aLane;
        const unsigned bStage = bsBase + (unsigned)(st * STAGE_H * 2) + bLane;
        #pragma unroll
        for (int k16 = 0; k16 < 2; k16++) {
            unsigned af[4][4], bf[4][2];
            #pragma unroll
            for (int mi = 0; mi < 4; mi++)
                ldsm_x4(af[mi][0], af[mi][1], af[mi][2], af[mi][3],
                        aStage + (unsigned)((mi * 16 * BKH + k16 * 16) * 2));
            #pragma unroll
            for (int ni = 0; ni < 4; ni++)
                ldsm_x2(bf[ni][0], bf[ni][1],
                        bStage + (unsigned)((ni * 8 * BKH + k16 * 16) * 2));
            #pragma unroll
            for (int mi = 0; mi < 4; mi++)
                #pragma unroll
                for (int ni = 0; ni < 4; ni++)
                    mma_bf16(acc[mi][ni],
                             af[mi][0], af[mi][1], af[mi][2], af[mi][3],
                             bf[ni][0], bf[ni][1]);
        }
        st  = (st  == N_STAGE - 1) ? 0 : st + 1;
        pst = (pst == N_STAGE - 1) ? 0 : pst + 1;
    }
}

// Epilogue index helpers: r0 = m0+wm+mi*16+g ; r1 = r0+8 ; c = n0+wn+ni*8+2*tig

// ---------------- GEMM 1: QKV projections (bf16 out) ------------------------
__global__ void __launch_bounds__(256, 2) k_qkv(
        const float* __restrict__ bq, const float* __restrict__ bk,
        const float* __restrict__ bv) {
    const bf16* W; const float* Bi; bf16* out;
    if (blockIdx.z == 0)      { W = g_wq; Bi = bq; out = g_q; }
    else if (blockIdx.z == 1) { W = g_wk; Bi = bk; out = g_k; }
    else                      { W = g_wv; Bi = bv; out = g_v; }
    const int m0 = blockIdx.x * 128;   // token
    const int n0 = blockIdx.y * 128;   // out channel
    float acc[4][4][4] = {};
    gemm_core(g_hn + (size_t)m0 * C_DIM, W + (size_t)n0 * C_DIM, C_DIM, C_DIM, C_DIM, acc);

    const int tid = threadIdx.x, lane = tid & 31, warp = tid >> 5;
    const int g = lane >> 2, tig = lane & 3;
    const int wm = (warp >> 2) * 64, wn = (warp & 3) * 32;
    #pragma unroll
    for (int mi = 0; mi < 4; mi++) {
        int r0 = m0 + wm + mi * 16 + g;
        #pragma unroll
        for (int ni = 0; ni < 4; ni++) {
            int c = n0 + wn + ni * 8 + 2 * tig;
            float b0v = Bi[c], b1v = Bi[c + 1];
            *reinterpret_cast<bf162*>(&out[(size_t)r0 * C_DIM + c]) =
                __float22bfloat162_rn(make_float2(acc[mi][ni][0] + b0v, acc[mi][ni][1] + b1v));
            *reinterpret_cast<bf162*>(&out[(size_t)(r0 + 8) * C_DIM + c]) =
                __float22bfloat162_rn(make_float2(acc[mi][ni][2] + b0v, acc[mi][ni][3] + b1v));
        }
    }
}

// ---------------- GEMM 2: S = scale * Q K^T (fp32 scores out) ---------------
__global__ void __launch_bounds__(256, 2) k_qk(float scale) {
    const int f  = blockIdx.z;
    const int m0 = blockIdx.x * 128;
    const int n0 = blockIdx.y * 128;
    const bf16* Q  = g_q + (size_t)f * HW * C_DIM + (size_t)m0 * C_DIM;
    const bf16* Km = g_k + (size_t)f * HW * C_DIM + (size_t)n0 * C_DIM;
    float* P = g_p + (size_t)f * HW * HW;
    float acc[4][4][4] = {};
    gemm_core(Q, Km, C_DIM, C_DIM, C_DIM, acc);

    const int tid = threadIdx.x, lane = tid & 31, warp = tid >> 5;
    const int g = lane >> 2, tig = lane & 3;
    const int wm = (warp >> 2) * 64, wn = (warp & 3) * 32;
    #pragma unroll
    for (int mi = 0; mi < 4; mi++) {
        int r0 = m0 + wm + mi * 16 + g;
        #pragma unroll
        for (int ni = 0; ni < 4; ni++) {
            int c = n0 + wn + ni * 8 + 2 * tig;
            *reinterpret_cast<float2*>(&P[(size_t)r0 * HW + c]) =
                make_float2(acc[mi][ni][0] * scale, acc[mi][ni][1] * scale);
            *reinterpret_cast<float2*>(&P[(size_t)(r0 + 8) * HW + c]) =
                make_float2(acc[mi][ni][2] * scale, acc[mi][ni][3] * scale);
        }
    }
}

// ---------------- row softmax: fp32 in, bf16 out -----------------------------
__global__ void softmax_rows() {
    const int row = blockIdx.x;
    const float4* p4 = reinterpret_cast<const float4*>(g_p + (size_t)row * HW);
    const int tid  = threadIdx.x;
    const int lane = tid & 31;
    const int wid  = tid >> 5;
    __shared__ float red[8];

    float4 v = p4[tid];
    float mx = fmaxf(fmaxf(v.x, v.y), fmaxf(v.z, v.w));
    #pragma unroll
    for (int o = 16; o > 0; o >>= 1) mx = fmaxf(mx, __shfl_xor_sync(0xffffffffu, mx, o));
    if (lane == 0) red[wid] = mx;
    __syncthreads();
    mx = red[lane & 7];
    #pragma unroll
    for (int o = 4; o > 0; o >>= 1) mx = fmaxf(mx, __shfl_xor_sync(0xffffffffu, mx, o));

    v.x = __expf(v.x - mx); v.y = __expf(v.y - mx);
    v.z = __expf(v.z - mx); v.w = __expf(v.w - mx);
    float s = v.x + v.y + v.z + v.w;
    #pragma unroll
    for (int o = 16; o > 0; o >>= 1) s += __shfl_xor_sync(0xffffffffu, s, o);
    __syncthreads();
    if (lane == 0) red[wid] = s;
    __syncthreads();
    s = red[lane & 7];
    #pragma unroll
    for (int o = 4; o > 0; o >>= 1) s += __shfl_xor_sync(0xffffffffu, s, o);

    float inv = __frcp_rn(s);
    bf162 h0 = __float22bfloat162_rn(make_float2(v.x * inv, v.y * inv));
    bf162 h1 = __float22bfloat162_rn(make_float2(v.z * inv, v.w * inv));
    bf162* ob = reinterpret_cast<bf162*>(g_pb + (size_t)row * HW);
    ob[tid * 2]     = h0;
    ob[tid * 2 + 1] = h1;
}

// ---------------- GEMM 3: O = P V (bf16 out) ---------------------------------
__global__ void __launch_bounds__(256, 2) k_pv() {
    const int f  = blockIdx.z;
    const int m0 = blockIdx.x * 128;   // query token
    const int n0 = blockIdx.y * 128;   // channel
    const bf16* P  = g_pb + (size_t)f * HW * HW + (size_t)m0 * HW;
    const bf16* Vt = g_vt + (size_t)f * C_DIM * HW + (size_t)n0 * HW;
    float acc[4][4][4] = {};
    gemm_core(P, Vt, HW, HW, HW, acc);

    const int tid = threadIdx.x, lane = tid & 31, warp = tid >> 5;
    const int g = lane >> 2, tig = lane & 3;
    const int wm = (warp >> 2) * 64, wn = (warp & 3) * 32;
    bf16* O = g_ao + (size_t)f * HW * C_DIM;
    #pragma unroll
    for (int mi = 0; mi < 4; mi++) {
        int r0 = m0 + wm + mi * 16 + g;
        #pragma unroll
        for (int ni = 0; ni < 4; ni++) {
            int c = n0 + wn + ni * 8 + 2 * tig;
            *reinterpret_cast<bf162*>(&O[(size_t)r0 * C_DIM + c]) =
                __float22bfloat162_rn(make_float2(acc[mi][ni][0], acc[mi][ni][1]));
            *reinterpret_cast<bf162*>(&O[(size_t)(r0 + 8) * C_DIM + c]) =
                __float22bfloat162_rn(make_float2(acc[mi][ni][2], acc[mi][ni][3]));
        }
    }
}

// ---------------- GEMM 4: out proj + bias + residual (fp32 out) -------------
__global__ void __launch_bounds__(256, 2) k_out(
        const float* __restrict__ bo,
        const float* __restrict__ x, float* __restrict__ y) {
    const int m0 = blockIdx.x * 128;   // out channel
    const int n0 = blockIdx.y * 128;   // spatial position
    float acc[4][4][4] = {};
    gemm_core(g_wo + (size_t)m0 * C_DIM, g_ao + (size_t)n0 * C_DIM, C_DIM, C_DIM, C_DIM, acc);

    const int tid = threadIdx.x, lane = tid & 31, warp = tid >> 5;
    const int g = lane >> 2, tig = lane & 3;
    const int wm = (warp >> 2) * 64, wn = (warp & 3) * 32;
    #pragma unroll
    for (int mi = 0; mi < 4; mi++) {
        int r0 = m0 + wm + mi * 16 + g;
        float bo0 = bo[r0], bo1 = bo[r0 + 8];
        #pragma unroll
        for (int ni = 0; ni < 4; ni++) {
            int c = n0 + wn + ni * 8 + 2 * tig;
            size_t i00 = (size_t)r0 * S_TOT + c;
            size_t i10 = (size_t)(r0 + 8) * S_TOT + c;
            float2 x0 = *reinterpret_cast<const float2*>(&x[i00]);
            float2 x1 = *reinterpret_cast<const float2*>(&x[i10]);
            *reinterpret_cast<float2*>(&y[i00]) =
                make_float2(acc[mi][ni][0] + bo0 + x0.x, acc[mi][ni][1] + bo0 + x0.y);
            *reinterpret_cast<float2*>(&y[i10]) =
                make_float2(acc[mi][ni][2] + bo1 + x1.x, acc[mi][ni][3] + bo1 + x1.y);
        }
    }
}

// ---------------- launch ------------------------------------------------------
extern "C" void kernel_launch(void* const* d_in, const int* in_sizes, int n_in,
                              void* d_out, int out_size) {
    const float* x     = (const float*)d_in[0];
    const float* gamma = (const float*)d_in[1];
    const float* beta  = (const float*)d_in[2];
    const float* wq    = (const float*)d_in[3];
    const float* bq    = (const float*)d_in[4];
    const float* wk    = (const float*)d_in[5];
    const float* bk    = (const float*)d_in[6];
    const float* wv    = (const float*)d_in[7];
    const float* bv    = (const float*)d_in[8];
    const float* wo    = (const float*)d_in[9];
    const float* bo    = (const float*)d_in[10];
    float* y = (float*)d_out;

    w_convert<<<dim3(256, 4), 256>>>(wq, wk, wv, wo);
    gn_stats1<<<dim3(NG, 8), 256>>>(x);
    gn_stats2<<<1, 32>>>();
    gn_apply_t<<<dim3(S_TOT / 32, C_DIM / 32), dim3(32, 8)>>>(x, gamma, beta);

    k_qkv<<<dim3(S_TOT / 128, C_DIM / 128, 3), 256>>>(bq, bk, bv);

    v_transpose<<<dim3(HW / 32, C_DIM / 32, T_FR), dim3(32, 8)>>>();

    const float scale = 0.044194173824159216f;  // 512^-0.5
    k_qk<<<dim3(HW / 128, HW / 128, T_FR), 256>>>(scale);

    softmax_rows<<<S_TOT, 256>>>();

    k_pv<<<dim3(HW / 128, C_DIM / 128, T_FR), 256>>>();

    k_out<<<dim3(C_DIM / 128, S_TOT / 128), 256>>>(bo, x, y);
}

// round 15
// speedup vs baseline: 8.5088x; 1.0927x over previous
#include <cuda_runtime.h>
#include <cuda_bf16.h>
#include <math.h>
#include <stdint.h>

// Problem constants (b=1, c=512, t=16, h=w=32)
#define C_DIM 512
#define T_FR 16
#define HW 1024          // h*w tokens per frame
#define S_TOT 16384      // t*h*w
#define NG 32            // groups
#define CPG 16           // channels per group

typedef __nv_bfloat16 bf16;
typedef __nv_bfloat162 bf162;

// ---------------- scratch (device globals; no allocation allowed) ----------
__device__ __align__(16) bf16  g_hn[S_TOT * C_DIM];        // token-major [s][c]
__device__ __align__(16) bf16  g_q [S_TOT * C_DIM];        // [s][c]
__device__ __align__(16) bf16  g_k [S_TOT * C_DIM];        // [s][c]
__device__ __align__(16) bf16  g_v [S_TOT * C_DIM];        // [s][c]
__device__ __align__(16) float g_p [T_FR * HW * HW];       // [f][i][j] fp32 scores
__device__ __align__(16) bf16  g_pb[T_FR * HW * HW];       // bf16 probs
__device__ __align__(16) bf16  g_ao[S_TOT * C_DIM];        // [s][c]
__device__ __align__(16) bf16  g_wq[C_DIM * C_DIM];
__device__ __align__(16) bf16  g_wk[C_DIM * C_DIM];
__device__ __align__(16) bf16  g_wv[C_DIM * C_DIM];
__device__ __align__(16) bf16  g_wo[C_DIM * C_DIM];
__device__ float g_part[NG * 8 * 2];
__device__ float g_mean[NG];
__device__ float g_rstd[NG];

// ======================= elementwise kernels ================================

__global__ void w_convert(const float* __restrict__ w0, const float* __restrict__ w1,
                          const float* __restrict__ w2, const float* __restrict__ w3) {
    const float* src; bf16* dst;
    if (blockIdx.y == 0)      { src = w0; dst = g_wq; }
    else if (blockIdx.y == 1) { src = w1; dst = g_wk; }
    else if (blockIdx.y == 2) { src = w2; dst = g_wv; }
    else                      { src = w3; dst = g_wo; }
    int i = blockIdx.x * 256 + threadIdx.x;
    float4 v = reinterpret_cast<const float4*>(src)[i];
    bf162* d = reinterpret_cast<bf162*>(dst) + i * 2;
    d[0] = __float22bfloat162_rn(make_float2(v.x, v.y));
    d[1] = __float22bfloat162_rn(make_float2(v.z, v.w));
}

__global__ void gn_stats1(const float* __restrict__ x) {
    const int g = blockIdx.x;
    const int chunk = blockIdx.y;
    const int n_chunk = (CPG * S_TOT) / 8;
    const float* xp = x + (size_t)g * CPG * S_TOT + (size_t)chunk * n_chunk;
    float s = 0.f, ss = 0.f;
    for (int i = threadIdx.x; i < n_chunk / 4; i += 256) {
        float4 v = reinterpret_cast<const float4*>(xp)[i];
        s  += v.x + v.y + v.z + v.w;
        ss += v.x * v.x + v.y * v.y + v.z * v.z + v.w * v.w;
    }
    #pragma unroll
    for (int o = 16; o > 0; o >>= 1) {
        s  += __shfl_xor_sync(0xffffffffu, s, o);
        ss += __shfl_xor_sync(0xffffffffu, ss, o);
    }
    __shared__ float rs[8], rss[8];
    if ((threadIdx.x & 31) == 0) { rs[threadIdx.x >> 5] = s; rss[threadIdx.x >> 5] = ss; }
    __syncthreads();
    if (threadIdx.x == 0) {
        float ts = 0.f, tss = 0.f;
        #pragma unroll
        for (int i = 0; i < 8; i++) { ts += rs[i]; tss += rss[i]; }
        g_part[(g * 8 + chunk) * 2 + 0] = ts;
        g_part[(g * 8 + chunk) * 2 + 1] = tss;
    }
}

__global__ void gn_stats2() {
    int g = threadIdx.x;
    if (g >= NG) return;
    float s = 0.f, ss = 0.f;
    #pragma unroll
    for (int i = 0; i < 8; i++) {
        s  += g_part[(g * 8 + i) * 2 + 0];
        ss += g_part[(g * 8 + i) * 2 + 1];
    }
    const float inv_n = 1.0f / (float)(CPG * S_TOT);
    float m = s * inv_n;
    float var = ss * inv_n - m * m;
    g_mean[g] = m;
    g_rstd[g] = rsqrtf(var + 1e-6f);
}

__global__ void gn_apply_t(const float* __restrict__ x,
                           const float* __restrict__ gamma,
                           const float* __restrict__ beta) {
    __shared__ float tile[32][33];
    const int s0 = blockIdx.x * 32;
    const int c0 = blockIdx.y * 32;
    const int tx = threadIdx.x, ty = threadIdx.y;
    #pragma unroll
    for (int j = 0; j < 4; j++) {
        int cl = ty + j * 8;
        tile[cl][tx] = x[(size_t)(c0 + cl) * S_TOT + s0 + tx];
    }
    __syncthreads();
    int c = c0 + tx;
    int g = c >> 4;
    float m = g_mean[g], r = g_rstd[g];
    float ga = gamma[c], be = beta[c];
    #pragma unroll
    for (int j = 0; j < 4; j++) {
        int sl = ty + j * 8;
        g_hn[(size_t)(s0 + sl) * C_DIM + c] =
            __float2bfloat16_rn((tile[tx][sl] - m) * r * ga + be);
    }
}

__global__ void softmax_rows() {
    const int row = blockIdx.x;
    const float4* p4 = reinterpret_cast<const float4*>(g_p + (size_t)row * HW);
    const int tid  = threadIdx.x;
    const int lane = tid & 31;
    const int wid  = tid >> 5;
    __shared__ float red[8];

    float4 v = p4[tid];
    float mx = fmaxf(fmaxf(v.x, v.y), fmaxf(v.z, v.w));
    #pragma unroll
    for (int o = 16; o > 0; o >>= 1) mx = fmaxf(mx, __shfl_xor_sync(0xffffffffu, mx, o));
    if (lane == 0) red[wid] = mx;
    __syncthreads();
    mx = red[lane & 7];
    #pragma unroll
    for (int o = 4; o > 0; o >>= 1) mx = fmaxf(mx, __shfl_xor_sync(0xffffffffu, mx, o));

    v.x = __expf(v.x - mx); v.y = __expf(v.y - mx);
    v.z = __expf(v.z - mx); v.w = __expf(v.w - mx);
    float s = v.x + v.y + v.z + v.w;
    #pragma unroll
    for (int o = 16; o > 0; o >>= 1) s += __shfl_xor_sync(0xffffffffu, s, o);
    __syncthreads();
    if (lane == 0) red[wid] = s;
    __syncthreads();
    s = red[lane & 7];
    #pragma unroll
    for (int o = 4; o > 0; o >>= 1) s += __shfl_xor_sync(0xffffffffu, s, o);

    float inv = __frcp_rn(s);
    bf162 h0 = __float22bfloat162_rn(make_float2(v.x * inv, v.y * inv));
    bf162 h1 = __float22bfloat162_rn(make_float2(v.z * inv, v.w * inv));
    bf162* ob = reinterpret_cast<bf162*>(g_pb + (size_t)row * HW);
    ob[tid * 2]     = h0;
    ob[tid * 2 + 1] = h1;
}

// ======================= bf16 mma.sync GEMM core (BK=64) =====================
// out[m][n] = sum_k A[m][k] * B[n][k]  (NT, both K-contiguous, bf16)
// Block tile 128x128, BK=64, 3-stage cp.async, 8 warps (2x4), warp 64x32.

#define BKH   72                 // 64 + 8 pad halves; 144B row stride (36 words)
#define STGB  (128 * BKH * 2)    // bytes per stage (A or B)
#define VKH   136                // V tile: 128 + 8 pad halves; 272B stride
#define VSTGB (64 * VKH * 2)     // bytes per V stage
#define NSTG  3
#define SMEM_DYN (2 * NSTG * STGB)   // 110592 bytes

__device__ __forceinline__ void cp16(unsigned dst, const void* src) {
    asm volatile("cp.async.cg.shared.global [%0], [%1], 16;\n" :: "r"(dst), "l"(src));
}
__device__ __forceinline__ void cp_commit() { asm volatile("cp.async.commit_group;\n"); }
__device__ __forceinline__ void cp_wait1()  { asm volatile("cp.async.wait_group 1;\n"); }

__device__ __forceinline__ void ldsm_x4(unsigned* r, unsigned addr) {
    asm volatile("ldmatrix.sync.aligned.m8n8.x4.shared.b16 {%0,%1,%2,%3}, [%4];"
                 : "=r"(r[0]), "=r"(r[1]), "=r"(r[2]), "=r"(r[3]) : "r"(addr));
}
__device__ __forceinline__ void ldsm_x2(unsigned& r0, unsigned& r1, unsigned addr) {
    asm volatile("ldmatrix.sync.aligned.m8n8.x2.shared.b16 {%0,%1}, [%2];"
                 : "=r"(r0), "=r"(r1) : "r"(addr));
}
__device__ __forceinline__ void ldsm_x2t(unsigned& r0, unsigned& r1, unsigned addr) {
    asm volatile("ldmatrix.sync.aligned.m8n8.x2.trans.shared.b16 {%0,%1}, [%2];"
                 : "=r"(r0), "=r"(r1) : "r"(addr));
}

__device__ __forceinline__ void mma_bf16(float c[4],
                                         unsigned a0, unsigned a1, unsigned a2, unsigned a3,
                                         unsigned b0, unsigned b1) {
    asm volatile(
        "mma.sync.aligned.m16n8k16.row.col.f32.bf16.bf16.f32 "
        "{%0,%1,%2,%3},{%4,%5,%6,%7},{%8,%9},{%0,%1,%2,%3};\n"
        : "+f"(c[0]), "+f"(c[1]), "+f"(c[2]), "+f"(c[3])
        : "r"(a0), "r"(a1), "r"(a2), "r"(a3), "r"(b0), "r"(b1));
}

// ---- NT core: A and B both [row][k] K-contiguous, 128 rows each ------------
__device__ __forceinline__ void gemm_nt(const bf16* __restrict__ A,
                                        const bf16* __restrict__ B,
                                        int lda, int ldb, int K,
                                        unsigned aS, unsigned bS,
                                        float acc[4][4][4]) {
    const int tid = threadIdx.x, lane = tid & 31, warp = tid >> 5;
    const int wm = (warp >> 2) * 64, wn = (warp & 3) * 32;

    const int row = tid >> 3, q = tid & 7;   // + i*32 rows per chunk
    const bf16* Ap = A + (size_t)row * lda + q * 8;
    const bf16* Bp = B + (size_t)row * ldb + q * 8;
    const unsigned aD = aS + (unsigned)((row * BKH + q * 8) * 2);
    const unsigned bD = bS + (unsigned)((row * BKH + q * 8) * 2);

    const unsigned aL = (unsigned)(((wm + (lane & 15)) * BKH + (lane >> 4) * 8) * 2);
    const unsigned bL = (unsigned)(((wn + (lane & 7))  * BKH + ((lane >> 3) & 1) * 8) * 2);

    const int n_iter = K >> 6;

    #pragma unroll
    for (int s = 0; s < 2; s++) {
        const int k0 = s << 6;
        #pragma unroll
        for (int i = 0; i < 4; i++) {
            cp16(aD + s * STGB + i * (32 * BKH * 2), Ap + (size_t)i * 32 * lda + k0);
            cp16(bD + s * STGB + i * (32 * BKH * 2), Bp + (size_t)i * 32 * ldb + k0);
        }
        cp_commit();
    }

    int st = 0, pst = 2;
    for (int it = 0; it < n_iter; it++) {
        cp_wait1();
        __syncthreads();

        if (it + 2 < n_iter) {
            const int k0 = (it + 2) << 6;
            #pragma unroll
            for (int i = 0; i < 4; i++) {
                cp16(aD + pst * STGB + i * (32 * BKH * 2), Ap + (size_t)i * 32 * lda + k0);
                cp16(bD + pst * STGB + i * (32 * BKH * 2), Bp + (size_t)i * 32 * ldb + k0);
            }
        }
        cp_commit();

        const unsigned aStage = aS + st * STGB + aL;
        const unsigned bStage = bS + st * STGB + bL;
        #pragma unroll
        for (int s4 = 0; s4 < 4; s4++) {
            unsigned af[4][4], bf[4][2];
            #pragma unroll
            for (int mi = 0; mi < 4; mi++)
                ldsm_x4(af[mi], aStage + (unsigned)((mi * 16 * BKH + s4 * 16) * 2));
            #pragma unroll
            for (int ni = 0; ni < 4; ni++)
                ldsm_x2(bf[ni][0], bf[ni][1], bStage + (unsigned)((ni * 8 * BKH + s4 * 16) * 2));
            #pragma unroll
            for (int mi = 0; mi < 4; mi++)
                #pragma unroll
                for (int ni = 0; ni < 4; ni++)
                    mma_bf16(acc[mi][ni], af[mi][0], af[mi][1], af[mi][2], af[mi][3],
                             bf[ni][0], bf[ni][1]);
        }
        st  = (st  == NSTG - 1) ? 0 : st + 1;
        pst = (pst == NSTG - 1) ? 0 : pst + 1;
    }
}

// ---- PV core: A = P [row][k]; B = V [k][n] loaded native, trans-ldmatrix ---
__device__ __forceinline__ void gemm_pv(const bf16* __restrict__ A,
                                        const bf16* __restrict__ V,   // + n0 offset
                                        int lda, int ldv, int K,
                                        unsigned aS, unsigned bS,
                                        float acc[4][4][4]) {
    const int tid = threadIdx.x, lane = tid & 31, warp = tid >> 5;
    const int wm = (warp >> 2) * 64, wn = (warp & 3) * 32;

    const int row = tid >> 3, q = tid & 7;
    const bf16* Ap = A + (size_t)row * lda + q * 8;
    const unsigned aD = aS + (unsigned)((row * BKH + q * 8) * 2);

    const int vrow = tid >> 4, vq = tid & 15;   // + i*16 rows per chunk
    const bf16* Vp = V + (size_t)vrow * ldv + vq * 8;
    const unsigned vD = bS + (unsigned)((vrow * VKH + vq * 8) * 2);

    const unsigned aL  = (unsigned)(((wm + (lane & 15)) * BKH + (lane >> 4) * 8) * 2);
    const unsigned bLT = (unsigned)(((lane & 15) * VKH) * 2);

    const int n_iter = K >> 6;

    #pragma unroll
    for (int s = 0; s < 2; s++) {
        const int k0 = s << 6;
        #pragma unroll
        for (int i = 0; i < 4; i++) {
            cp16(aD + s * STGB  + i * (32 * BKH * 2), Ap + (size_t)i * 32 * lda + k0);
            cp16(vD + s * VSTGB + i * (16 * VKH * 2), Vp + (size_t)(k0 + i * 16) * ldv);
        }
        cp_commit();
    }

    int st = 0, pst = 2;
    for (int it = 0; it < n_iter; it++) {
        cp_wait1();
        __syncthreads();

        if (it + 2 < n_iter) {
            const int k0 = (it + 2) << 6;
            #pragma unroll
            for (int i = 0; i < 4; i++) {
                cp16(aD + pst * STGB  + i * (32 * BKH * 2), Ap + (size_t)i * 32 * lda + k0);
                cp16(vD + pst * VSTGB + i * (16 * VKH * 2), Vp + (size_t)(k0 + i * 16) * ldv);
            }
        }
        cp_commit();

        const unsigned aStage = aS + st * STGB + aL;
        const unsigned bStage = bS + st * VSTGB + bLT;
        #pragma unroll
        for (int s4 = 0; s4 < 4; s4++) {
            unsigned af[4][4], bf[4][2];
            #pragma unroll
            for (int mi = 0; mi < 4; mi++)
                ldsm_x4(af[mi], aStage + (unsigned)((mi * 16 * BKH + s4 * 16) * 2));
            #pragma unroll
            for (int ni = 0; ni < 4; ni++)
                ldsm_x2t(bf[ni][0], bf[ni][1],
                         bStage + (unsigned)((s4 * 16 * VKH + wn + ni * 8) * 2));
            #pragma unroll
            for (int mi = 0; mi < 4; mi++)
                #pragma unroll
                for (int ni = 0; ni < 4; ni++)
                    mma_bf16(acc[mi][ni], af[mi][0], af[mi][1], af[mi][2], af[mi][3],
                             bf[ni][0], bf[ni][1]);
        }
        st  = (st  == NSTG - 1) ? 0 : st + 1;
        pst = (pst == NSTG - 1) ? 0 : pst + 1;
    }
}

#define GEMM_PREAMBLE() \
    extern __shared__ char dynraw[]; \
    const unsigned smb = (unsigned)__cvta_generic_to_shared(dynraw); \
    const unsigned aS = smb; \
    const unsigned bS = smb + NSTG * STGB; \
    const int tid = threadIdx.x, lane = tid & 31, warp = tid >> 5; \
    const int g = lane >> 2, tig = lane & 3; \
    const int wm = (warp >> 2) * 64, wn = (warp & 3) * 32;

// ---------------- GEMM 1: QKV projections (bf16 out) ------------------------
__global__ void __launch_bounds__(256, 2) k_qkv(
        const float* __restrict__ bq, const float* __restrict__ bk,
        const float* __restrict__ bv) {
    GEMM_PREAMBLE();
    const bf16* W; const float* Bi; bf16* out;
    if (blockIdx.z == 0)      { W = g_wq; Bi = bq; out = g_q; }
    else if (blockIdx.z == 1) { W = g_wk; Bi = bk; out = g_k; }
    else                      { W = g_wv; Bi = bv; out = g_v; }
    const int m0 = blockIdx.x * 128;   // token
    const int n0 = blockIdx.y * 128;   // out channel
    float acc[4][4][4] = {};
    gemm_nt(g_hn + (size_t)m0 * C_DIM, W + (size_t)n0 * C_DIM, C_DIM, C_DIM, C_DIM,
            aS, bS, acc);

    #pragma unroll
    for (int mi = 0; mi < 4; mi++) {
        int r0 = m0 + wm + mi * 16 + g;
        #pragma unroll
        for (int ni = 0; ni < 4; ni++) {
            int c = n0 + wn + ni * 8 + 2 * tig;
            float b0v = Bi[c], b1v = Bi[c + 1];
            *reinterpret_cast<bf162*>(&out[(size_t)r0 * C_DIM + c]) =
                __float22bfloat162_rn(make_float2(acc[mi][ni][0] + b0v, acc[mi][ni][1] + b1v));
            *reinterpret_cast<bf162*>(&out[(size_t)(r0 + 8) * C_DIM + c]) =
                __float22bfloat162_rn(make_float2(acc[mi][ni][2] + b0v, acc[mi][ni][3] + b1v));
        }
    }
}

// ---------------- GEMM 2: S = scale * Q K^T (fp32 out) ----------------------
__global__ void __launch_bounds__(256, 2) k_qk(float scale) {
    GEMM_PREAMBLE();
    const int f  = blockIdx.z;
    const int m0 = blockIdx.x * 128;
    const int n0 = blockIdx.y * 128;
    const bf16* Q  = g_q + (size_t)f * HW * C_DIM + (size_t)m0 * C_DIM;
    const bf16* Km = g_k + (size_t)f * HW * C_DIM + (size_t)n0 * C_DIM;
    float* P = g_p + (size_t)f * HW * HW;
    float acc[4][4][4] = {};
    gemm_nt(Q, Km, C_DIM, C_DIM, C_DIM, aS, bS, acc);

    #pragma unroll
    for (int mi = 0; mi < 4; mi++) {
        int r0 = m0 + wm + mi * 16 + g;
        #pragma unroll
        for (int ni = 0; ni < 4; ni++) {
            int c = n0 + wn + ni * 8 + 2 * tig;
            *reinterpret_cast<float2*>(&P[(size_t)r0 * HW + c]) =
                make_float2(acc[mi][ni][0] * scale, acc[mi][ni][1] * scale);
            *reinterpret_cast<float2*>(&P[(size_t)(r0 + 8) * HW + c]) =
                make_float2(acc[mi][ni][2] * scale, acc[mi][ni][3] * scale);
        }
    }
}

// ---------------- GEMM 3: O = P V (bf16 out, V native layout) ---------------
__global__ void __launch_bounds__(256, 2) k_pv() {
    GEMM_PREAMBLE();
    const int f  = blockIdx.z;
    const int m0 = blockIdx.x * 128;   // query token
    const int n0 = blockIdx.y * 128;   // channel
    const bf16* P = g_pb + (size_t)f * HW * HW + (size_t)m0 * HW;
    const bf16* V = g_v  + (size_t)f * HW * C_DIM + n0;
    float acc[4][4][4] = {};
    gemm_pv(P, V, HW, C_DIM, HW, aS, bS, acc);

    bf16* O = g_ao + (size_t)f * HW * C_DIM;
    #pragma unroll
    for (int mi = 0; mi < 4; mi++) {
        int r0 = m0 + wm + mi * 16 + g;
        #pragma unroll
        for (int ni = 0; ni < 4; ni++) {
            int c = n0 + wn + ni * 8 + 2 * tig;
            *reinterpret_cast<bf162*>(&O[(size_t)r0 * C_DIM + c]) =
                __float22bfloat162_rn(make_float2(acc[mi][ni][0], acc[mi][ni][1]));
            *reinterpret_cast<bf162*>(&O[(size_t)(r0 + 8) * C_DIM + c]) =
                __float22bfloat162_rn(make_float2(acc[mi][ni][2], acc[mi][ni][3]));
        }
    }
}

// ---------------- GEMM 4: out proj + bias + residual (fp32 out) -------------
__global__ void __launch_bounds__(256, 2) k_out(
        const float* __restrict__ bo,
        const float* __restrict__ x, float* __restrict__ y) {
    GEMM_PREAMBLE();
    const int m0 = blockIdx.x * 128;   // out channel
    const int n0 = blockIdx.y * 128;   // spatial position
    float acc[4][4][4] = {};
    gemm_nt(g_wo + (size_t)m0 * C_DIM, g_ao + (size_t)n0 * C_DIM, C_DIM, C_DIM, C_DIM,
            aS, bS, acc);

    #pragma unroll
    for (int mi = 0; mi < 4; mi++) {
        int r0 = m0 + wm + mi * 16 + g;
        float bo0 = bo[r0], bo1 = bo[r0 + 8];
        #pragma unroll
        for (int ni = 0; ni < 4; ni++) {
            int c = n0 + wn + ni * 8 + 2 * tig;
            size_t i00 = (size_t)r0 * S_TOT + c;
            size_t i10 = (size_t)(r0 + 8) * S_TOT + c;
            float2 x0 = *reinterpret_cast<const float2*>(&x[i00]);
            float2 x1 = *reinterpret_cast<const float2*>(&x[i10]);
            *reinterpret_cast<float2*>(&y[i00]) =
                make_float2(acc[mi][ni][0] + bo0 + x0.x, acc[mi][ni][1] + bo0 + x0.y);
            *reinterpret_cast<float2*>(&y[i10]) =
                make_float2(acc[mi][ni][2] + bo1 + x1.x, acc[mi][ni][3] + bo1 + x1.y);
        }
    }
}

// ---------------- launch ------------------------------------------------------
extern "C" void kernel_launch(void* const* d_in, const int* in_sizes, int n_in,
                              void* d_out, int out_size) {
    const float* x     = (const float*)d_in[0];
    const float* gamma = (const float*)d_in[1];
    const float* beta  = (const float*)d_in[2];
    const float* wq    = (const float*)d_in[3];
    const float* bq    = (const float*)d_in[4];
    const float* wk    = (const float*)d_in[5];
    const float* bk    = (const float*)d_in[6];
    const float* wv    = (const float*)d_in[7];
    const float* bv    = (const float*)d_in[8];
    const float* wo    = (const float*)d_in[9];
    const float* bo    = (const float*)d_in[10];
    float* y = (float*)d_out;

    cudaFuncSetAttribute(k_qkv, cudaFuncAttributeMaxDynamicSharedMemorySize, SMEM_DYN);
    cudaFuncSetAttribute(k_qk,  cudaFuncAttributeMaxDynamicSharedMemorySize, SMEM_DYN);
    cudaFuncSetAttribute(k_pv,  cudaFuncAttributeMaxDynamicSharedMemorySize, SMEM_DYN);
    cudaFuncSetAttribute(k_out, cudaFuncAttributeMaxDynamicSharedMemorySize, SMEM_DYN);

    w_convert<<<dim3(256, 4), 256>>>(wq, wk, wv, wo);
    gn_stats1<<<dim3(NG, 8), 256>>>(x);
    gn_stats2<<<1, 32>>>();
    gn_apply_t<<<dim3(S_TOT / 32, C_DIM / 32), dim3(32, 8)>>>(x, gamma, beta);

    k_qkv<<<dim3(S_TOT / 128, C_DIM / 128, 3), 256, SMEM_DYN>>>(bq, bk, bv);

    const float scale = 0.044194173824159216f;  // 512^-0.5
    k_qk<<<dim3(HW / 128, HW / 128, T_FR), 256, SMEM_DYN>>>(scale);

    softmax_rows<<<S_TOT, 256>>>();

    k_pv<<<dim3(HW / 128, C_DIM / 128, T_FR), 256, SMEM_DYN>>>();

    k_out<<<dim3(C_DIM / 128, S_TOT / 128), 256, SMEM_DYN>>>(bo, x, y);
}